// round 1
// baseline (speedup 1.0000x reference)
#include <cuda_runtime.h>
#include <cstdint>

#define NNODES  50000
#define NEDGES  640000
#define HID     128
#define NRBF    50
#define TILE    128
#define NT      512
#define CUTOFF_F 5.0f

// RBF constants: offsets = linspace(0,5,50) -> step = 5/49
#define RBF_W   (CUTOFF_F / 49.0f)
#define RBF_IW  (49.0f / CUTOFF_F)

typedef unsigned long long ull;

__device__ float g_agg[NNODES * HID];

// ---------- packed f32x2 helpers ----------
__device__ __forceinline__ void fma2(ull &acc, ull a, ull b) {
    asm("fma.rn.f32x2 %0, %1, %2, %0;" : "+l"(acc) : "l"(a), "l"(b));
}
__device__ __forceinline__ ull bcast2(float x) {
    ull r; asm("mov.b64 %0, {%1, %1};" : "=l"(r) : "f"(x)); return r;
}
__device__ __forceinline__ ull pack2(float x, float y) {
    ull r; asm("mov.b64 %0, {%1, %2};" : "=l"(r) : "f"(x), "f"(y)); return r;
}
__device__ __forceinline__ float2 unpack2(ull v) {
    float2 f; asm("mov.b64 {%0, %1}, %2;" : "=f"(f.x), "=f"(f.y) : "l"(v)); return f;
}
__device__ __forceinline__ void red4(float* p, float a, float b, float c, float d) {
    asm volatile("red.global.add.v4.f32 [%0], {%1,%2,%3,%4};"
                 :: "l"(p), "f"(a), "f"(b), "f"(c), "f"(d) : "memory");
}
__device__ __forceinline__ float silu_f(float x) {
    return x / (1.0f + __expf(-x));
}

// ---------- zero scratch ----------
__global__ void zero_kernel() {
    float4* p = (float4*)g_agg;
    const int n = NNODES * HID / 4;
    for (int i = blockIdx.x * blockDim.x + threadIdx.x; i < n; i += gridDim.x * blockDim.x)
        p[i] = make_float4(0.f, 0.f, 0.f, 0.f);
}

// ---------- edge kernel ----------
// smem: fw1[50*128] | fw2[128*128] | rbf[128*50] | s1[128*128] | dist[128] | cut[128] | row[128] | col[128]
#define EDGE_SMEM_FLOATS (NRBF*HID + HID*HID + TILE*NRBF + TILE*HID + 2*TILE)
#define EDGE_SMEM_BYTES  ((EDGE_SMEM_FLOATS + 2*TILE) * 4)

__global__ __launch_bounds__(NT, 1)
void edge_kernel(const float* __restrict__ hin, const float* __restrict__ pos,
                 const void* __restrict__ ei,
                 const float* __restrict__ fw1, const float* __restrict__ fb1,
                 const float* __restrict__ fw2, const float* __restrict__ fb2)
{
    extern __shared__ float sm[];
    float* fw1_s  = sm;
    float* fw2_s  = fw1_s + NRBF * HID;
    float* rbf_s  = fw2_s + HID * HID;
    float* s1_s   = rbf_s + TILE * NRBF;
    float* dist_s = s1_s + TILE * HID;
    float* cut_s  = dist_s + TILE;
    int*   row_s  = (int*)(cut_s + TILE);
    int*   col_s  = row_s + TILE;
    __shared__ int s_is64;

    const int tid = threadIdx.x;

    // dtype detection for edge_index (int64 vs int32)
    if (tid == 0) {
        const unsigned* u = (const unsigned*)ei;
        unsigned acc = 0;
        #pragma unroll
        for (int i = 0; i < 64; i++) acc |= u[2*i + 1];
        s_is64 = (acc == 0);
    }

    // stage weights to smem
    {
        const float4* s1 = (const float4*)fw1; float4* d1 = (float4*)fw1_s;
        for (int i = tid; i < NRBF*HID/4; i += NT) d1[i] = s1[i];
        const float4* s2 = (const float4*)fw2; float4* d2 = (float4*)fw2_s;
        for (int i = tid; i < HID*HID/4; i += NT) d2[i] = s2[i];
    }
    __syncthreads();

    // per-edge metadata: indices, dist, cutoff
    const int is64 = s_is64;
    const int ebase = blockIdx.x * TILE;
    for (int i = tid; i < TILE; i += NT) {
        int e = ebase + i;
        int r, c;
        if (is64) {
            r = (int)((const long long*)ei)[e];
            c = (int)((const long long*)ei)[NEDGES + e];
        } else {
            r = ((const int*)ei)[e];
            c = ((const int*)ei)[NEDGES + e];
        }
        float dx = pos[r*3+0] - pos[c*3+0];
        float dy = pos[r*3+1] - pos[c*3+1];
        float dz = pos[r*3+2] - pos[c*3+2];
        float d  = sqrtf(dx*dx + dy*dy + dz*dz + 1e-8f);
        dist_s[i] = d;
        float ct = 0.f;
        if (d <= CUTOFF_F)
            ct = 0.5f * (__cosf(d * (3.14159265358979323846f / CUTOFF_F)) + 1.0f);
        cut_s[i] = ct;
        row_s[i] = r;
        col_s[i] = c;
    }
    __syncthreads();

    // RBF expansion
    for (int idx = tid; idx < TILE * NRBF; idx += NT) {
        int e = idx / NRBF;
        int k = idx - e * NRBF;
        float t = (dist_s[e] - (float)k * RBF_W) * RBF_IW;
        rbf_s[idx] = __expf(-0.5f * t * t);
    }
    __syncthreads();

    const int eg0 = (tid >> 4) * 4;   // 4 edges per thread
    const int c0  = (tid & 15) * 8;   // 8 cols per thread

    // ---- GEMM1: rbf[128x50] @ fw1[50x128] + fb1, SiLU -> s1 ----
    ull acc[4][4];
    {
        float4 ba = *(const float4*)(fb1 + c0);
        float4 bb = *(const float4*)(fb1 + c0 + 4);
        ull i0 = pack2(ba.x, ba.y), i1 = pack2(ba.z, ba.w);
        ull i2 = pack2(bb.x, bb.y), i3 = pack2(bb.z, bb.w);
        #pragma unroll
        for (int i = 0; i < 4; i++) { acc[i][0]=i0; acc[i][1]=i1; acc[i][2]=i2; acc[i][3]=i3; }
    }
    {
        const float* rbase = rbf_s + eg0 * NRBF;
        #pragma unroll 2
        for (int k = 0; k < NRBF; k++) {
            ull a0 = bcast2(rbase[k]);
            ull a1 = bcast2(rbase[k +   NRBF]);
            ull a2 = bcast2(rbase[k + 2*NRBF]);
            ull a3 = bcast2(rbase[k + 3*NRBF]);
            const ulonglong2* wp = (const ulonglong2*)(fw1_s + k*HID + c0);
            ulonglong2 w01 = wp[0], w23 = wp[1];
            fma2(acc[0][0],a0,w01.x); fma2(acc[0][1],a0,w01.y); fma2(acc[0][2],a0,w23.x); fma2(acc[0][3],a0,w23.y);
            fma2(acc[1][0],a1,w01.x); fma2(acc[1][1],a1,w01.y); fma2(acc[1][2],a1,w23.x); fma2(acc[1][3],a1,w23.y);
            fma2(acc[2][0],a2,w01.x); fma2(acc[2][1],a2,w01.y); fma2(acc[2][2],a2,w23.x); fma2(acc[2][3],a2,w23.y);
            fma2(acc[3][0],a3,w01.x); fma2(acc[3][1],a3,w01.y); fma2(acc[3][2],a3,w23.x); fma2(acc[3][3],a3,w23.y);
        }
    }
    #pragma unroll
    for (int i = 0; i < 4; i++) {
        float4 o0, o1; float2 v;
        v = unpack2(acc[i][0]); o0.x = silu_f(v.x); o0.y = silu_f(v.y);
        v = unpack2(acc[i][1]); o0.z = silu_f(v.x); o0.w = silu_f(v.y);
        v = unpack2(acc[i][2]); o1.x = silu_f(v.x); o1.y = silu_f(v.y);
        v = unpack2(acc[i][3]); o1.z = silu_f(v.x); o1.w = silu_f(v.y);
        *(float4*)(s1_s + (eg0+i)*HID + c0)     = o0;
        *(float4*)(s1_s + (eg0+i)*HID + c0 + 4) = o1;
    }
    __syncthreads();

    // ---- GEMM2: s1[128x128] @ fw2[128x128] + fb2 ----
    {
        float4 ba = *(const float4*)(fb2 + c0);
        float4 bb = *(const float4*)(fb2 + c0 + 4);
        ull i0 = pack2(ba.x, ba.y), i1 = pack2(ba.z, ba.w);
        ull i2 = pack2(bb.x, bb.y), i3 = pack2(bb.z, bb.w);
        #pragma unroll
        for (int i = 0; i < 4; i++) { acc[i][0]=i0; acc[i][1]=i1; acc[i][2]=i2; acc[i][3]=i3; }
    }
    {
        const float* sbase = s1_s + eg0 * HID;
        #pragma unroll 2
        for (int k = 0; k < HID; k++) {
            ull a0 = bcast2(sbase[k]);
            ull a1 = bcast2(sbase[k +   HID]);
            ull a2 = bcast2(sbase[k + 2*HID]);
            ull a3 = bcast2(sbase[k + 3*HID]);
            const ulonglong2* wp = (const ulonglong2*)(fw2_s + k*HID + c0);
            ulonglong2 w01 = wp[0], w23 = wp[1];
            fma2(acc[0][0],a0,w01.x); fma2(acc[0][1],a0,w01.y); fma2(acc[0][2],a0,w23.x); fma2(acc[0][3],a0,w23.y);
            fma2(acc[1][0],a1,w01.x); fma2(acc[1][1],a1,w01.y); fma2(acc[1][2],a1,w23.x); fma2(acc[1][3],a1,w23.y);
            fma2(acc[2][0],a2,w01.x); fma2(acc[2][1],a2,w01.y); fma2(acc[2][2],a2,w23.x); fma2(acc[2][3],a2,w23.y);
            fma2(acc[3][0],a3,w01.x); fma2(acc[3][1],a3,w01.y); fma2(acc[3][2],a3,w23.x); fma2(acc[3][3],a3,w23.y);
        }
    }

    // ---- epilogue: msg = h[col] * w * cut, scatter-add to agg[row] ----
    #pragma unroll
    for (int i = 0; i < 4; i++) {
        int e = eg0 + i;
        float ct = cut_s[e];
        int col = col_s[e];
        int row = row_s[e];
        float4 h0 = *(const float4*)(hin + col*HID + c0);
        float4 h1 = *(const float4*)(hin + col*HID + c0 + 4);
        float2 v0 = unpack2(acc[i][0]);
        float2 v1 = unpack2(acc[i][1]);
        float2 v2 = unpack2(acc[i][2]);
        float2 v3 = unpack2(acc[i][3]);
        float* dst = g_agg + row*HID + c0;
        red4(dst,     h0.x*v0.x*ct, h0.y*v0.y*ct, h0.z*v1.x*ct, h0.w*v1.y*ct);
        red4(dst + 4, h1.x*v2.x*ct, h1.y*v2.y*ct, h1.z*v3.x*ct, h1.w*v3.y*ct);
    }
}

// ---------- node kernel ----------
// smem: iw1[128*128] | iw2[128*128] | x[128*128]
#define NODE_SMEM_BYTES (3 * HID * HID * 4)

__global__ __launch_bounds__(NT, 1)
void node_kernel(const float* __restrict__ hin, float* __restrict__ out,
                 const float* __restrict__ iw1, const float* __restrict__ ib1,
                 const float* __restrict__ iw2, const float* __restrict__ ib2)
{
    extern __shared__ float sm[];
    float* iw1_s = sm;
    float* iw2_s = iw1_s + HID * HID;
    float* x_s   = iw2_s + HID * HID;

    const int tid = threadIdx.x;
    const int nbase = blockIdx.x * TILE;

    {
        const float4* s1 = (const float4*)iw1; float4* d1 = (float4*)iw1_s;
        for (int i = tid; i < HID*HID/4; i += NT) d1[i] = s1[i];
        const float4* s2 = (const float4*)iw2; float4* d2 = (float4*)iw2_s;
        for (int i = tid; i < HID*HID/4; i += NT) d2[i] = s2[i];
    }
    // load agg tile
    {
        const float4* ag = (const float4*)g_agg;
        float4* xv = (float4*)x_s;
        for (int idx = tid; idx < TILE * HID / 4; idx += NT) {
            int n = nbase + (idx >> 5);
            xv[idx] = (n < NNODES) ? ag[n * (HID/4) + (idx & 31)]
                                   : make_float4(0.f, 0.f, 0.f, 0.f);
        }
    }
    __syncthreads();

    const int ng0 = (tid >> 4) * 4;
    const int c0  = (tid & 15) * 8;

    ull acc[4][4];
    {
        float4 ba = *(const float4*)(ib1 + c0);
        float4 bb = *(const float4*)(ib1 + c0 + 4);
        ull i0 = pack2(ba.x, ba.y), i1 = pack2(ba.z, ba.w);
        ull i2 = pack2(bb.x, bb.y), i3 = pack2(bb.z, bb.w);
        #pragma unroll
        for (int i = 0; i < 4; i++) { acc[i][0]=i0; acc[i][1]=i1; acc[i][2]=i2; acc[i][3]=i3; }
    }
    {
        const float* xbase = x_s + ng0 * HID;
        #pragma unroll 2
        for (int k = 0; k < HID; k++) {
            ull a0 = bcast2(xbase[k]);
            ull a1 = bcast2(xbase[k +   HID]);
            ull a2 = bcast2(xbase[k + 2*HID]);
            ull a3 = bcast2(xbase[k + 3*HID]);
            const ulonglong2* wp = (const ulonglong2*)(iw1_s + k*HID + c0);
            ulonglong2 w01 = wp[0], w23 = wp[1];
            fma2(acc[0][0],a0,w01.x); fma2(acc[0][1],a0,w01.y); fma2(acc[0][2],a0,w23.x); fma2(acc[0][3],a0,w23.y);
            fma2(acc[1][0],a1,w01.x); fma2(acc[1][1],a1,w01.y); fma2(acc[1][2],a1,w23.x); fma2(acc[1][3],a1,w23.y);
            fma2(acc[2][0],a2,w01.x); fma2(acc[2][1],a2,w01.y); fma2(acc[2][2],a2,w23.x); fma2(acc[2][3],a2,w23.y);
            fma2(acc[3][0],a3,w01.x); fma2(acc[3][1],a3,w01.y); fma2(acc[3][2],a3,w23.x); fma2(acc[3][3],a3,w23.y);
        }
    }
    __syncthreads();   // all reads of x_s done
    #pragma unroll
    for (int i = 0; i < 4; i++) {
        float4 o0, o1; float2 v;
        v = unpack2(acc[i][0]); o0.x = silu_f(v.x); o0.y = silu_f(v.y);
        v = unpack2(acc[i][1]); o0.z = silu_f(v.x); o0.w = silu_f(v.y);
        v = unpack2(acc[i][2]); o1.x = silu_f(v.x); o1.y = silu_f(v.y);
        v = unpack2(acc[i][3]); o1.z = silu_f(v.x); o1.w = silu_f(v.y);
        *(float4*)(x_s + (ng0+i)*HID + c0)     = o0;
        *(float4*)(x_s + (ng0+i)*HID + c0 + 4) = o1;
    }
    __syncthreads();

    {
        float4 ba = *(const float4*)(ib2 + c0);
        float4 bb = *(const float4*)(ib2 + c0 + 4);
        ull i0 = pack2(ba.x, ba.y), i1 = pack2(ba.z, ba.w);
        ull i2 = pack2(bb.x, bb.y), i3 = pack2(bb.z, bb.w);
        #pragma unroll
        for (int i = 0; i < 4; i++) { acc[i][0]=i0; acc[i][1]=i1; acc[i][2]=i2; acc[i][3]=i3; }
    }
    {
        const float* xbase = x_s + ng0 * HID;
        #pragma unroll 2
        for (int k = 0; k < HID; k++) {
            ull a0 = bcast2(xbase[k]);
            ull a1 = bcast2(xbase[k +   HID]);
            ull a2 = bcast2(xbase[k + 2*HID]);
            ull a3 = bcast2(xbase[k + 3*HID]);
            const ulonglong2* wp = (const ulonglong2*)(iw2_s + k*HID + c0);
            ulonglong2 w01 = wp[0], w23 = wp[1];
            fma2(acc[0][0],a0,w01.x); fma2(acc[0][1],a0,w01.y); fma2(acc[0][2],a0,w23.x); fma2(acc[0][3],a0,w23.y);
            fma2(acc[1][0],a1,w01.x); fma2(acc[1][1],a1,w01.y); fma2(acc[1][2],a1,w23.x); fma2(acc[1][3],a1,w23.y);
            fma2(acc[2][0],a2,w01.x); fma2(acc[2][1],a2,w01.y); fma2(acc[2][2],a2,w23.x); fma2(acc[2][3],a2,w23.y);
            fma2(acc[3][0],a3,w01.x); fma2(acc[3][1],a3,w01.y); fma2(acc[3][2],a3,w23.x); fma2(acc[3][3],a3,w23.y);
        }
    }

    #pragma unroll
    for (int i = 0; i < 4; i++) {
        int n = ng0 + i + nbase;
        if (n >= NNODES) continue;
        float4 h0 = *(const float4*)(hin + n*HID + c0);
        float4 h1 = *(const float4*)(hin + n*HID + c0 + 4);
        float2 v0 = unpack2(acc[i][0]);
        float2 v1 = unpack2(acc[i][1]);
        float2 v2 = unpack2(acc[i][2]);
        float2 v3 = unpack2(acc[i][3]);
        float4 o0 = make_float4(h0.x + v0.x, h0.y + v0.y, h0.z + v1.x, h0.w + v1.y);
        float4 o1 = make_float4(h1.x + v2.x, h1.y + v2.y, h1.z + v3.x, h1.w + v3.y);
        *(float4*)(out + n*HID + c0)     = o0;
        *(float4*)(out + n*HID + c0 + 4) = o1;
    }
}

extern "C" void kernel_launch(void* const* d_in, const int* in_sizes, int n_in,
                              void* d_out, int out_size)
{
    const float* h    = (const float*)d_in[0];
    const float* pos  = (const float*)d_in[1];
    const void*  ei   = d_in[2];
    const float* fw1  = (const float*)d_in[3];
    const float* fb1  = (const float*)d_in[4];
    const float* fw2  = (const float*)d_in[5];
    const float* fb2  = (const float*)d_in[6];
    const float* iw1  = (const float*)d_in[7];
    const float* ib1  = (const float*)d_in[8];
    const float* iw2  = (const float*)d_in[9];
    const float* ib2  = (const float*)d_in[10];
    float* out = (float*)d_out;

    cudaFuncSetAttribute(edge_kernel, cudaFuncAttributeMaxDynamicSharedMemorySize, EDGE_SMEM_BYTES);
    cudaFuncSetAttribute(node_kernel, cudaFuncAttributeMaxDynamicSharedMemorySize, NODE_SMEM_BYTES);

    zero_kernel<<<1184, 512>>>();
    edge_kernel<<<NEDGES / TILE, NT, EDGE_SMEM_BYTES>>>(h, pos, ei, fw1, fb1, fw2, fb2);
    node_kernel<<<(NNODES + TILE - 1) / TILE, NT, NODE_SMEM_BYTES>>>(h, out, iw1, ib1, iw2, ib2);
}

// round 2
// speedup vs baseline: 1.0703x; 1.0703x over previous
#include <cuda_runtime.h>
#include <cstdint>

#define NNODES  50000
#define NEDGES  640000
#define HID     128
#define NRBF    50
#define TILE    128
#define NT      512
#define CUTOFF_F 5.0f
#define NTILES_E (NEDGES / TILE)
#define NTILES_N ((NNODES + TILE - 1) / TILE)
#define GRID_P  152

// RBF constants: offsets = linspace(0,5,50) -> step = 5/49
#define RBF_W   (CUTOFF_F / 49.0f)
#define RBF_IW  (49.0f / CUTOFF_F)

typedef unsigned long long ull;

__device__ float g_agg[NNODES * HID];
__device__ unsigned g_ctr_edge;
__device__ unsigned g_ctr_node;

// ---------- packed f32x2 helpers ----------
__device__ __forceinline__ void fma2(ull &acc, ull a, ull b) {
    asm("fma.rn.f32x2 %0, %1, %2, %0;" : "+l"(acc) : "l"(a), "l"(b));
}
__device__ __forceinline__ ull bcast2(float x) {
    ull r; asm("mov.b64 %0, {%1, %1};" : "=l"(r) : "f"(x)); return r;
}
__device__ __forceinline__ ull pack2(float x, float y) {
    ull r; asm("mov.b64 %0, {%1, %2};" : "=l"(r) : "f"(x), "f"(y)); return r;
}
__device__ __forceinline__ float2 unpack2(ull v) {
    float2 f; asm("mov.b64 {%0, %1}, %2;" : "=f"(f.x), "=f"(f.y) : "l"(v)); return f;
}
__device__ __forceinline__ void red4(float* p, float a, float b, float c, float d) {
    asm volatile("red.global.add.v4.f32 [%0], {%1,%2,%3,%4};"
                 :: "l"(p), "f"(a), "f"(b), "f"(c), "f"(d) : "memory");
}
__device__ __forceinline__ float silu_f(float x) {
    return x / (1.0f + __expf(-x));
}

// ---------- zero scratch + counters ----------
__global__ void zero_kernel() {
    if (blockIdx.x == 0 && threadIdx.x == 0) { g_ctr_edge = 0u; g_ctr_node = 0u; }
    float4* p = (float4*)g_agg;
    const int n = NNODES * HID / 4;
    for (int i = blockIdx.x * blockDim.x + threadIdx.x; i < n; i += gridDim.x * blockDim.x)
        p[i] = make_float4(0.f, 0.f, 0.f, 0.f);
}

// ---------- persistent edge kernel ----------
// smem: fw1[50*128] | fw2[128*128] | rbf[128*50] | s1[128*128] | dist[128] | cut[128] | row[128] | col[128]
#define EDGE_SMEM_FLOATS (NRBF*HID + HID*HID + TILE*NRBF + TILE*HID + 2*TILE)
#define EDGE_SMEM_BYTES  ((EDGE_SMEM_FLOATS + 2*TILE) * 4)

__global__ __launch_bounds__(NT, 1)
void edge_kernel(const float* __restrict__ hin, const float* __restrict__ pos,
                 const void* __restrict__ ei,
                 const float* __restrict__ fw1, const float* __restrict__ fb1,
                 const float* __restrict__ fw2, const float* __restrict__ fb2)
{
    extern __shared__ float sm[];
    float* fw1_s  = sm;
    float* fw2_s  = fw1_s + NRBF * HID;
    float* rbf_s  = fw2_s + HID * HID;
    float* s1_s   = rbf_s + TILE * NRBF;
    float* dist_s = s1_s + TILE * HID;
    float* cut_s  = dist_s + TILE;
    int*   row_s  = (int*)(cut_s + TILE);
    int*   col_s  = row_s + TILE;
    __shared__ int s_is64;
    __shared__ int s_tile;

    const int tid = threadIdx.x;

    // dtype detection for edge_index (int64 vs int32)
    if (tid == 0) {
        const unsigned* u = (const unsigned*)ei;
        unsigned acc = 0;
        #pragma unroll
        for (int i = 0; i < 64; i++) acc |= u[2*i + 1];
        s_is64 = (acc == 0);
    }

    // stage weights to smem ONCE per CTA
    {
        const float4* w1 = (const float4*)fw1; float4* d1 = (float4*)fw1_s;
        for (int i = tid; i < NRBF*HID/4; i += NT) d1[i] = w1[i];
        const float4* w2 = (const float4*)fw2; float4* d2 = (float4*)fw2_s;
        for (int i = tid; i < HID*HID/4; i += NT) d2[i] = w2[i];
    }
    __syncthreads();
    const int is64 = s_is64;

    // bias pre-pack (loop-invariant)
    const int eg0 = (tid >> 4) * 4;   // 4 edges per thread
    const int c0  = (tid & 15) * 8;   // 8 cols per thread
    ull b1p[4], b2p[4];
    {
        float4 ba = *(const float4*)(fb1 + c0);
        float4 bb = *(const float4*)(fb1 + c0 + 4);
        b1p[0] = pack2(ba.x, ba.y); b1p[1] = pack2(ba.z, ba.w);
        b1p[2] = pack2(bb.x, bb.y); b1p[3] = pack2(bb.z, bb.w);
        ba = *(const float4*)(fb2 + c0);
        bb = *(const float4*)(fb2 + c0 + 4);
        b2p[0] = pack2(ba.x, ba.y); b2p[1] = pack2(ba.z, ba.w);
        b2p[2] = pack2(bb.x, bb.y); b2p[3] = pack2(bb.z, bb.w);
    }

    while (true) {
        __syncthreads();   // protect smem reuse (prev tile fully consumed) + s_tile
        if (tid == 0) s_tile = (int)atomicAdd(&g_ctr_edge, 1u);
        __syncthreads();
        const int tile = s_tile;
        if (tile >= NTILES_E) break;
        const int ebase = tile * TILE;

        // ---- per-edge metadata ----
        if (tid < TILE) {
            int e = ebase + tid;
            int r, c;
            if (is64) {
                r = (int)((const long long*)ei)[e];
                c = (int)((const long long*)ei)[NEDGES + e];
            } else {
                r = ((const int*)ei)[e];
                c = ((const int*)ei)[NEDGES + e];
            }
            float dx = pos[r*3+0] - pos[c*3+0];
            float dy = pos[r*3+1] - pos[c*3+1];
            float dz = pos[r*3+2] - pos[c*3+2];
            float d  = sqrtf(dx*dx + dy*dy + dz*dz + 1e-8f);
            dist_s[tid] = d;
            float ct = 0.f;
            if (d <= CUTOFF_F)
                ct = 0.5f * (__cosf(d * (3.14159265358979323846f / CUTOFF_F)) + 1.0f);
            cut_s[tid] = ct;
            row_s[tid] = r;
            col_s[tid] = c;
        }
        __syncthreads();

        // ---- RBF expansion ----
        for (int idx = tid; idx < TILE * NRBF; idx += NT) {
            int e = idx / NRBF;
            int k = idx - e * NRBF;
            float t = (dist_s[e] - (float)k * RBF_W) * RBF_IW;
            rbf_s[idx] = __expf(-0.5f * t * t);
        }
        __syncthreads();

        // ---- GEMM1: rbf[128x50] @ fw1[50x128] + fb1, SiLU -> s1 ----
        ull acc[4][4];
        #pragma unroll
        for (int i = 0; i < 4; i++) {
            acc[i][0]=b1p[0]; acc[i][1]=b1p[1]; acc[i][2]=b1p[2]; acc[i][3]=b1p[3];
        }
        {
            const float* rbase = rbf_s + eg0 * NRBF;
            #pragma unroll 2
            for (int k = 0; k < NRBF; k++) {
                ull a0 = bcast2(rbase[k]);
                ull a1 = bcast2(rbase[k +   NRBF]);
                ull a2 = bcast2(rbase[k + 2*NRBF]);
                ull a3 = bcast2(rbase[k + 3*NRBF]);
                const ulonglong2* wp = (const ulonglong2*)(fw1_s + k*HID + c0);
                ulonglong2 w01 = wp[0], w23 = wp[1];
                fma2(acc[0][0],a0,w01.x); fma2(acc[0][1],a0,w01.y); fma2(acc[0][2],a0,w23.x); fma2(acc[0][3],a0,w23.y);
                fma2(acc[1][0],a1,w01.x); fma2(acc[1][1],a1,w01.y); fma2(acc[1][2],a1,w23.x); fma2(acc[1][3],a1,w23.y);
                fma2(acc[2][0],a2,w01.x); fma2(acc[2][1],a2,w01.y); fma2(acc[2][2],a2,w23.x); fma2(acc[2][3],a2,w23.y);
                fma2(acc[3][0],a3,w01.x); fma2(acc[3][1],a3,w01.y); fma2(acc[3][2],a3,w23.x); fma2(acc[3][3],a3,w23.y);
            }
        }
        #pragma unroll
        for (int i = 0; i < 4; i++) {
            float4 o0, o1; float2 v;
            v = unpack2(acc[i][0]); o0.x = silu_f(v.x); o0.y = silu_f(v.y);
            v = unpack2(acc[i][1]); o0.z = silu_f(v.x); o0.w = silu_f(v.y);
            v = unpack2(acc[i][2]); o1.x = silu_f(v.x); o1.y = silu_f(v.y);
            v = unpack2(acc[i][3]); o1.z = silu_f(v.x); o1.w = silu_f(v.y);
            *(float4*)(s1_s + (eg0+i)*HID + c0)     = o0;
            *(float4*)(s1_s + (eg0+i)*HID + c0 + 4) = o1;
        }
        __syncthreads();

        // ---- GEMM2: s1[128x128] @ fw2[128x128] + fb2 ----
        #pragma unroll
        for (int i = 0; i < 4; i++) {
            acc[i][0]=b2p[0]; acc[i][1]=b2p[1]; acc[i][2]=b2p[2]; acc[i][3]=b2p[3];
        }
        {
            const float* sbase = s1_s + eg0 * HID;
            #pragma unroll 2
            for (int k = 0; k < HID; k++) {
                ull a0 = bcast2(sbase[k]);
                ull a1 = bcast2(sbase[k +   HID]);
                ull a2 = bcast2(sbase[k + 2*HID]);
                ull a3 = bcast2(sbase[k + 3*HID]);
                const ulonglong2* wp = (const ulonglong2*)(fw2_s + k*HID + c0);
                ulonglong2 w01 = wp[0], w23 = wp[1];
                fma2(acc[0][0],a0,w01.x); fma2(acc[0][1],a0,w01.y); fma2(acc[0][2],a0,w23.x); fma2(acc[0][3],a0,w23.y);
                fma2(acc[1][0],a1,w01.x); fma2(acc[1][1],a1,w01.y); fma2(acc[1][2],a1,w23.x); fma2(acc[1][3],a1,w23.y);
                fma2(acc[2][0],a2,w01.x); fma2(acc[2][1],a2,w01.y); fma2(acc[2][2],a2,w23.x); fma2(acc[2][3],a2,w23.y);
                fma2(acc[3][0],a3,w01.x); fma2(acc[3][1],a3,w01.y); fma2(acc[3][2],a3,w23.x); fma2(acc[3][3],a3,w23.y);
            }
        }

        // ---- epilogue: msg = h[col] * w * cut, scatter-add to agg[row] ----
        #pragma unroll
        for (int i = 0; i < 4; i++) {
            int e = eg0 + i;
            float ct = cut_s[e];
            int col = col_s[e];
            int row = row_s[e];
            float4 h0 = *(const float4*)(hin + col*HID + c0);
            float4 h1 = *(const float4*)(hin + col*HID + c0 + 4);
            float2 v0 = unpack2(acc[i][0]);
            float2 v1 = unpack2(acc[i][1]);
            float2 v2 = unpack2(acc[i][2]);
            float2 v3 = unpack2(acc[i][3]);
            float* dst = g_agg + row*HID + c0;
            red4(dst,     h0.x*v0.x*ct, h0.y*v0.y*ct, h0.z*v1.x*ct, h0.w*v1.y*ct);
            red4(dst + 4, h1.x*v2.x*ct, h1.y*v2.y*ct, h1.z*v3.x*ct, h1.w*v3.y*ct);
        }
    }
}

// ---------- persistent node kernel ----------
// smem: iw1[128*128] | iw2[128*128] | x[128*128]
#define NODE_SMEM_BYTES (3 * HID * HID * 4)

__global__ __launch_bounds__(NT, 1)
void node_kernel(const float* __restrict__ hin, float* __restrict__ out,
                 const float* __restrict__ iw1, const float* __restrict__ ib1,
                 const float* __restrict__ iw2, const float* __restrict__ ib2)
{
    extern __shared__ float sm[];
    float* iw1_s = sm;
    float* iw2_s = iw1_s + HID * HID;
    float* x_s   = iw2_s + HID * HID;
    __shared__ int s_tile;

    const int tid = threadIdx.x;

    {
        const float4* w1 = (const float4*)iw1; float4* d1 = (float4*)iw1_s;
        for (int i = tid; i < HID*HID/4; i += NT) d1[i] = w1[i];
        const float4* w2 = (const float4*)iw2; float4* d2 = (float4*)iw2_s;
        for (int i = tid; i < HID*HID/4; i += NT) d2[i] = w2[i];
    }

    const int ng0 = (tid >> 4) * 4;
    const int c0  = (tid & 15) * 8;
    ull b1p[4], b2p[4];
    {
        float4 ba = *(const float4*)(ib1 + c0);
        float4 bb = *(const float4*)(ib1 + c0 + 4);
        b1p[0] = pack2(ba.x, ba.y); b1p[1] = pack2(ba.z, ba.w);
        b1p[2] = pack2(bb.x, bb.y); b1p[3] = pack2(bb.z, bb.w);
        ba = *(const float4*)(ib2 + c0);
        bb = *(const float4*)(ib2 + c0 + 4);
        b2p[0] = pack2(ba.x, ba.y); b2p[1] = pack2(ba.z, ba.w);
        b2p[2] = pack2(bb.x, bb.y); b2p[3] = pack2(bb.z, bb.w);
    }

    while (true) {
        __syncthreads();   // prev tile's x_s reads done + s_tile protection
        if (tid == 0) s_tile = (int)atomicAdd(&g_ctr_node, 1u);
        __syncthreads();
        const int tile = s_tile;
        if (tile >= NTILES_N) break;
        const int nbase = tile * TILE;

        // load agg tile
        {
            const float4* ag = (const float4*)g_agg;
            float4* xv = (float4*)x_s;
            for (int idx = tid; idx < TILE * HID / 4; idx += NT) {
                int n = nbase + (idx >> 5);
                xv[idx] = (n < NNODES) ? ag[n * (HID/4) + (idx & 31)]
                                       : make_float4(0.f, 0.f, 0.f, 0.f);
            }
        }
        __syncthreads();

        ull acc[4][4];
        #pragma unroll
        for (int i = 0; i < 4; i++) {
            acc[i][0]=b1p[0]; acc[i][1]=b1p[1]; acc[i][2]=b1p[2]; acc[i][3]=b1p[3];
        }
        {
            const float* xbase = x_s + ng0 * HID;
            #pragma unroll 2
            for (int k = 0; k < HID; k++) {
                ull a0 = bcast2(xbase[k]);
                ull a1 = bcast2(xbase[k +   HID]);
                ull a2 = bcast2(xbase[k + 2*HID]);
                ull a3 = bcast2(xbase[k + 3*HID]);
                const ulonglong2* wp = (const ulonglong2*)(iw1_s + k*HID + c0);
                ulonglong2 w01 = wp[0], w23 = wp[1];
                fma2(acc[0][0],a0,w01.x); fma2(acc[0][1],a0,w01.y); fma2(acc[0][2],a0,w23.x); fma2(acc[0][3],a0,w23.y);
                fma2(acc[1][0],a1,w01.x); fma2(acc[1][1],a1,w01.y); fma2(acc[1][2],a1,w23.x); fma2(acc[1][3],a1,w23.y);
                fma2(acc[2][0],a2,w01.x); fma2(acc[2][1],a2,w01.y); fma2(acc[2][2],a2,w23.x); fma2(acc[2][3],a2,w23.y);
                fma2(acc[3][0],a3,w01.x); fma2(acc[3][1],a3,w01.y); fma2(acc[3][2],a3,w23.x); fma2(acc[3][3],a3,w23.y);
            }
        }
        __syncthreads();   // all reads of x_s done before overwrite
        #pragma unroll
        for (int i = 0; i < 4; i++) {
            float4 o0, o1; float2 v;
            v = unpack2(acc[i][0]); o0.x = silu_f(v.x); o0.y = silu_f(v.y);
            v = unpack2(acc[i][1]); o0.z = silu_f(v.x); o0.w = silu_f(v.y);
            v = unpack2(acc[i][2]); o1.x = silu_f(v.x); o1.y = silu_f(v.y);
            v = unpack2(acc[i][3]); o1.z = silu_f(v.x); o1.w = silu_f(v.y);
            *(float4*)(x_s + (ng0+i)*HID + c0)     = o0;
            *(float4*)(x_s + (ng0+i)*HID + c0 + 4) = o1;
        }
        __syncthreads();

        #pragma unroll
        for (int i = 0; i < 4; i++) {
            acc[i][0]=b2p[0]; acc[i][1]=b2p[1]; acc[i][2]=b2p[2]; acc[i][3]=b2p[3];
        }
        {
            const float* xbase = x_s + ng0 * HID;
            #pragma unroll 2
            for (int k = 0; k < HID; k++) {
                ull a0 = bcast2(xbase[k]);
                ull a1 = bcast2(xbase[k +   HID]);
                ull a2 = bcast2(xbase[k + 2*HID]);
                ull a3 = bcast2(xbase[k + 3*HID]);
                const ulonglong2* wp = (const ulonglong2*)(iw2_s + k*HID + c0);
                ulonglong2 w01 = wp[0], w23 = wp[1];
                fma2(acc[0][0],a0,w01.x); fma2(acc[0][1],a0,w01.y); fma2(acc[0][2],a0,w23.x); fma2(acc[0][3],a0,w23.y);
                fma2(acc[1][0],a1,w01.x); fma2(acc[1][1],a1,w01.y); fma2(acc[1][2],a1,w23.x); fma2(acc[1][3],a1,w23.y);
                fma2(acc[2][0],a2,w01.x); fma2(acc[2][1],a2,w01.y); fma2(acc[2][2],a2,w23.x); fma2(acc[2][3],a2,w23.y);
                fma2(acc[3][0],a3,w01.x); fma2(acc[3][1],a3,w01.y); fma2(acc[3][2],a3,w23.x); fma2(acc[3][3],a3,w23.y);
            }
        }

        #pragma unroll
        for (int i = 0; i < 4; i++) {
            int n = ng0 + i + nbase;
            if (n >= NNODES) continue;
            float4 h0 = *(const float4*)(hin + n*HID + c0);
            float4 h1 = *(const float4*)(hin + n*HID + c0 + 4);
            float2 v0 = unpack2(acc[i][0]);
            float2 v1 = unpack2(acc[i][1]);
            float2 v2 = unpack2(acc[i][2]);
            float2 v3 = unpack2(acc[i][3]);
            float4 o0 = make_float4(h0.x + v0.x, h0.y + v0.y, h0.z + v1.x, h0.w + v1.y);
            float4 o1 = make_float4(h1.x + v2.x, h1.y + v2.y, h1.z + v3.x, h1.w + v3.y);
            *(float4*)(out + n*HID + c0)     = o0;
            *(float4*)(out + n*HID + c0 + 4) = o1;
        }
    }
}

extern "C" void kernel_launch(void* const* d_in, const int* in_sizes, int n_in,
                              void* d_out, int out_size)
{
    const float* h    = (const float*)d_in[0];
    const float* pos  = (const float*)d_in[1];
    const void*  ei   = d_in[2];
    const float* fw1  = (const float*)d_in[3];
    const float* fb1  = (const float*)d_in[4];
    const float* fw2  = (const float*)d_in[5];
    const float* fb2  = (const float*)d_in[6];
    const float* iw1  = (const float*)d_in[7];
    const float* ib1  = (const float*)d_in[8];
    const float* iw2  = (const float*)d_in[9];
    const float* ib2  = (const float*)d_in[10];
    float* out = (float*)d_out;

    cudaFuncSetAttribute(edge_kernel, cudaFuncAttributeMaxDynamicSharedMemorySize, EDGE_SMEM_BYTES);
    cudaFuncSetAttribute(node_kernel, cudaFuncAttributeMaxDynamicSharedMemorySize, NODE_SMEM_BYTES);

    zero_kernel<<<1184, 512>>>();
    edge_kernel<<<GRID_P, NT, EDGE_SMEM_BYTES>>>(h, pos, ei, fw1, fb1, fw2, fb2);
    node_kernel<<<GRID_P, NT, NODE_SMEM_BYTES>>>(h, out, iw1, ib1, iw2, ib2);
}

// round 3
// speedup vs baseline: 4.3794x; 4.0917x over previous
#include <cuda_runtime.h>
#include <cstdint>

#define NNODES  50000
#define NEDGES  640000
#define HID     128
#define NRBF    50
#define TILE    128
#define NT      512
#define CUTOFF_F 5.0f
#define NTILES_N ((NNODES + TILE - 1) / TILE)
#define GRID_P  152

#define NBINS   16384
#define TSTEP   (CUTOFF_F / (float)(NBINS - 1))
#define TINV    ((float)(NBINS - 1) / CUTOFF_F)

// RBF constants: offsets = linspace(0,5,50) -> step = 5/49
#define RBF_W   (CUTOFF_F / 49.0f)
#define RBF_IW  (49.0f / CUTOFF_F)

typedef unsigned long long ull;

__device__ float g_agg[NNODES * HID];
__device__ float g_table[NBINS * HID];   // 8 MB: wf(d) = (silu(rbf@fw1+b1)@fw2+b2)*cut(d)
__device__ unsigned g_ctr_node;
__device__ int g_is64;

// ---------- packed f32x2 helpers ----------
__device__ __forceinline__ void fma2(ull &acc, ull a, ull b) {
    asm("fma.rn.f32x2 %0, %1, %2, %0;" : "+l"(acc) : "l"(a), "l"(b));
}
__device__ __forceinline__ ull bcast2(float x) {
    ull r; asm("mov.b64 %0, {%1, %1};" : "=l"(r) : "f"(x)); return r;
}
__device__ __forceinline__ ull pack2(float x, float y) {
    ull r; asm("mov.b64 %0, {%1, %2};" : "=l"(r) : "f"(x), "f"(y)); return r;
}
__device__ __forceinline__ float2 unpack2(ull v) {
    float2 f; asm("mov.b64 {%0, %1}, %2;" : "=f"(f.x), "=f"(f.y) : "l"(v)); return f;
}
__device__ __forceinline__ void red4(float* p, float a, float b, float c, float d) {
    asm volatile("red.global.add.v4.f32 [%0], {%1,%2,%3,%4};"
                 :: "l"(p), "f"(a), "f"(b), "f"(c), "f"(d) : "memory");
}
__device__ __forceinline__ float silu_f(float x) {
    return x / (1.0f + __expf(-x));
}

// ---------- zero scratch + counters + dtype flag ----------
__global__ void zero_kernel(const void* ei) {
    if (blockIdx.x == 0 && threadIdx.x == 0) {
        g_ctr_node = 0u;
        const unsigned* u = (const unsigned*)ei;
        unsigned acc = 0;
        #pragma unroll
        for (int i = 0; i < 64; i++) acc |= u[2*i + 1];
        g_is64 = (acc == 0);
    }
    float4* p = (float4*)g_agg;
    const int n = NNODES * HID / 4;
    for (int i = blockIdx.x * blockDim.x + threadIdx.x; i < n; i += gridDim.x * blockDim.x)
        p[i] = make_float4(0.f, 0.f, 0.f, 0.f);
}

// ---------- table build kernel: one CTA per 128-row tile, 128 CTAs ----------
// smem: fw1[50*128] | fw2[128*128] | rbf[128*50] | s1[128*128] | cut[128]
#define TBL_SMEM_FLOATS (NRBF*HID + HID*HID + TILE*NRBF + TILE*HID + TILE)
#define TBL_SMEM_BYTES  (TBL_SMEM_FLOATS * 4)

__global__ __launch_bounds__(NT, 1)
void table_kernel(const float* __restrict__ fw1, const float* __restrict__ fb1,
                  const float* __restrict__ fw2, const float* __restrict__ fb2)
{
    extern __shared__ float sm[];
    float* fw1_s  = sm;
    float* fw2_s  = fw1_s + NRBF * HID;
    float* rbf_s  = fw2_s + HID * HID;
    float* s1_s   = rbf_s + TILE * NRBF;
    float* cut_s  = s1_s + TILE * HID;

    const int tid = threadIdx.x;
    const int rbase = blockIdx.x * TILE;

    // stage weights
    {
        const float4* w1 = (const float4*)fw1; float4* d1 = (float4*)fw1_s;
        for (int i = tid; i < NRBF*HID/4; i += NT) d1[i] = w1[i];
        const float4* w2 = (const float4*)fw2; float4* d2 = (float4*)fw2_s;
        for (int i = tid; i < HID*HID/4; i += NT) d2[i] = w2[i];
    }

    // cutoff per row
    if (tid < TILE) {
        float d = (float)(rbase + tid) * TSTEP;
        cut_s[tid] = 0.5f * (__cosf(d * (3.14159265358979323846f / CUTOFF_F)) + 1.0f);
    }

    // RBF expansion
    for (int idx = tid; idx < TILE * NRBF; idx += NT) {
        int e = idx / NRBF;
        int k = idx - e * NRBF;
        float d = (float)(rbase + e) * TSTEP;
        float t = (d - (float)k * RBF_W) * RBF_IW;
        rbf_s[idx] = __expf(-0.5f * t * t);
    }
    __syncthreads();

    const int eg0 = (tid >> 4) * 4;
    const int c0  = (tid & 15) * 8;

    // GEMM1 + SiLU
    ull acc[4][4];
    {
        float4 ba = *(const float4*)(fb1 + c0);
        float4 bb = *(const float4*)(fb1 + c0 + 4);
        ull i0 = pack2(ba.x, ba.y), i1 = pack2(ba.z, ba.w);
        ull i2 = pack2(bb.x, bb.y), i3 = pack2(bb.z, bb.w);
        #pragma unroll
        for (int i = 0; i < 4; i++) { acc[i][0]=i0; acc[i][1]=i1; acc[i][2]=i2; acc[i][3]=i3; }
    }
    {
        const float* rb = rbf_s + eg0 * NRBF;
        #pragma unroll 2
        for (int k = 0; k < NRBF; k++) {
            ull a0 = bcast2(rb[k]);
            ull a1 = bcast2(rb[k +   NRBF]);
            ull a2 = bcast2(rb[k + 2*NRBF]);
            ull a3 = bcast2(rb[k + 3*NRBF]);
            const ulonglong2* wp = (const ulonglong2*)(fw1_s + k*HID + c0);
            ulonglong2 w01 = wp[0], w23 = wp[1];
            fma2(acc[0][0],a0,w01.x); fma2(acc[0][1],a0,w01.y); fma2(acc[0][2],a0,w23.x); fma2(acc[0][3],a0,w23.y);
            fma2(acc[1][0],a1,w01.x); fma2(acc[1][1],a1,w01.y); fma2(acc[1][2],a1,w23.x); fma2(acc[1][3],a1,w23.y);
            fma2(acc[2][0],a2,w01.x); fma2(acc[2][1],a2,w01.y); fma2(acc[2][2],a2,w23.x); fma2(acc[2][3],a2,w23.y);
            fma2(acc[3][0],a3,w01.x); fma2(acc[3][1],a3,w01.y); fma2(acc[3][2],a3,w23.x); fma2(acc[3][3],a3,w23.y);
        }
    }
    #pragma unroll
    for (int i = 0; i < 4; i++) {
        float4 o0, o1; float2 v;
        v = unpack2(acc[i][0]); o0.x = silu_f(v.x); o0.y = silu_f(v.y);
        v = unpack2(acc[i][1]); o0.z = silu_f(v.x); o0.w = silu_f(v.y);
        v = unpack2(acc[i][2]); o1.x = silu_f(v.x); o1.y = silu_f(v.y);
        v = unpack2(acc[i][3]); o1.z = silu_f(v.x); o1.w = silu_f(v.y);
        *(float4*)(s1_s + (eg0+i)*HID + c0)     = o0;
        *(float4*)(s1_s + (eg0+i)*HID + c0 + 4) = o1;
    }
    __syncthreads();

    // GEMM2 + bias, apply cut, store table
    {
        float4 ba = *(const float4*)(fb2 + c0);
        float4 bb = *(const float4*)(fb2 + c0 + 4);
        ull i0 = pack2(ba.x, ba.y), i1 = pack2(ba.z, ba.w);
        ull i2 = pack2(bb.x, bb.y), i3 = pack2(bb.z, bb.w);
        #pragma unroll
        for (int i = 0; i < 4; i++) { acc[i][0]=i0; acc[i][1]=i1; acc[i][2]=i2; acc[i][3]=i3; }
    }
    {
        const float* sb = s1_s + eg0 * HID;
        #pragma unroll 2
        for (int k = 0; k < HID; k++) {
            ull a0 = bcast2(sb[k]);
            ull a1 = bcast2(sb[k +   HID]);
            ull a2 = bcast2(sb[k + 2*HID]);
            ull a3 = bcast2(sb[k + 3*HID]);
            const ulonglong2* wp = (const ulonglong2*)(fw2_s + k*HID + c0);
            ulonglong2 w01 = wp[0], w23 = wp[1];
            fma2(acc[0][0],a0,w01.x); fma2(acc[0][1],a0,w01.y); fma2(acc[0][2],a0,w23.x); fma2(acc[0][3],a0,w23.y);
            fma2(acc[1][0],a1,w01.x); fma2(acc[1][1],a1,w01.y); fma2(acc[1][2],a1,w23.x); fma2(acc[1][3],a1,w23.y);
            fma2(acc[2][0],a2,w01.x); fma2(acc[2][1],a2,w01.y); fma2(acc[2][2],a2,w23.x); fma2(acc[2][3],a2,w23.y);
            fma2(acc[3][0],a3,w01.x); fma2(acc[3][1],a3,w01.y); fma2(acc[3][2],a3,w23.x); fma2(acc[3][3],a3,w23.y);
        }
    }
    #pragma unroll
    for (int i = 0; i < 4; i++) {
        int r = rbase + eg0 + i;
        float ct = cut_s[eg0 + i];
        float2 v0 = unpack2(acc[i][0]);
        float2 v1 = unpack2(acc[i][1]);
        float2 v2 = unpack2(acc[i][2]);
        float2 v3 = unpack2(acc[i][3]);
        float4 o0 = make_float4(v0.x*ct, v0.y*ct, v1.x*ct, v1.y*ct);
        float4 o1 = make_float4(v2.x*ct, v2.y*ct, v3.x*ct, v3.y*ct);
        *(float4*)(g_table + r*HID + c0)     = o0;
        *(float4*)(g_table + r*HID + c0 + 4) = o1;
    }
}

// ---------- edge gather/lerp/scatter kernel ----------
// 16 threads per edge, each handles 8 channels.
#define GNT 256
#define GGRID 1184

__global__ __launch_bounds__(GNT)
void gather_kernel(const float* __restrict__ hin, const float* __restrict__ pos,
                   const void* __restrict__ ei)
{
    const int is64 = g_is64;
    const int lane16 = threadIdx.x & 15;
    const int c0 = lane16 * 8;
    const int gpb = GNT / 16;                       // edge groups per block
    int g = blockIdx.x * gpb + (threadIdx.x >> 4);
    const int gstride = GGRID * gpb;

    for (; g < NEDGES; g += gstride) {
        int r, c;
        if (is64) {
            r = (int)__ldg((const long long*)ei + g);
            c = (int)__ldg((const long long*)ei + NEDGES + g);
        } else {
            r = __ldg((const int*)ei + g);
            c = __ldg((const int*)ei + NEDGES + g);
        }
        float dx = pos[r*3+0] - pos[c*3+0];
        float dy = pos[r*3+1] - pos[c*3+1];
        float dz = pos[r*3+2] - pos[c*3+2];
        float d  = sqrtf(dx*dx + dy*dy + dz*dz + 1e-8f);
        if (d > CUTOFF_F) continue;

        float t = d * TINV;
        int i0 = (int)t;
        if (i0 > NBINS - 2) i0 = NBINS - 2;
        float fr = t - (float)i0;

        const float* T0 = g_table + i0*HID + c0;
        float4 a0 = *(const float4*)(T0);
        float4 a1 = *(const float4*)(T0 + 4);
        float4 b0 = *(const float4*)(T0 + HID);
        float4 b1 = *(const float4*)(T0 + HID + 4);
        float4 h0 = *(const float4*)(hin + c*HID + c0);
        float4 h1 = *(const float4*)(hin + c*HID + c0 + 4);

        float w0 = fmaf(fr, b0.x - a0.x, a0.x);
        float w1 = fmaf(fr, b0.y - a0.y, a0.y);
        float w2 = fmaf(fr, b0.z - a0.z, a0.z);
        float w3 = fmaf(fr, b0.w - a0.w, a0.w);
        float w4 = fmaf(fr, b1.x - a1.x, a1.x);
        float w5 = fmaf(fr, b1.y - a1.y, a1.y);
        float w6 = fmaf(fr, b1.z - a1.z, a1.z);
        float w7 = fmaf(fr, b1.w - a1.w, a1.w);

        float* dst = g_agg + r*HID + c0;
        red4(dst,     h0.x*w0, h0.y*w1, h0.z*w2, h0.w*w3);
        red4(dst + 4, h1.x*w4, h1.y*w5, h1.z*w6, h1.w*w7);
    }
}

// ---------- persistent node kernel ----------
// smem: iw1[128*128] | iw2[128*128] | x[128*128]
#define NODE_SMEM_BYTES (3 * HID * HID * 4)

__global__ __launch_bounds__(NT, 1)
void node_kernel(const float* __restrict__ hin, float* __restrict__ out,
                 const float* __restrict__ iw1, const float* __restrict__ ib1,
                 const float* __restrict__ iw2, const float* __restrict__ ib2)
{
    extern __shared__ float sm[];
    float* iw1_s = sm;
    float* iw2_s = iw1_s + HID * HID;
    float* x_s   = iw2_s + HID * HID;
    __shared__ int s_tile;

    const int tid = threadIdx.x;

    {
        const float4* w1 = (const float4*)iw1; float4* d1 = (float4*)iw1_s;
        for (int i = tid; i < HID*HID/4; i += NT) d1[i] = w1[i];
        const float4* w2 = (const float4*)iw2; float4* d2 = (float4*)iw2_s;
        for (int i = tid; i < HID*HID/4; i += NT) d2[i] = w2[i];
    }

    const int ng0 = (tid >> 4) * 4;
    const int c0  = (tid & 15) * 8;
    ull b1p[4], b2p[4];
    {
        float4 ba = *(const float4*)(ib1 + c0);
        float4 bb = *(const float4*)(ib1 + c0 + 4);
        b1p[0] = pack2(ba.x, ba.y); b1p[1] = pack2(ba.z, ba.w);
        b1p[2] = pack2(bb.x, bb.y); b1p[3] = pack2(bb.z, bb.w);
        ba = *(const float4*)(ib2 + c0);
        bb = *(const float4*)(ib2 + c0 + 4);
        b2p[0] = pack2(ba.x, ba.y); b2p[1] = pack2(ba.z, ba.w);
        b2p[2] = pack2(bb.x, bb.y); b2p[3] = pack2(bb.z, bb.w);
    }

    while (true) {
        __syncthreads();
        if (tid == 0) s_tile = (int)atomicAdd(&g_ctr_node, 1u);
        __syncthreads();
        const int tile = s_tile;
        if (tile >= NTILES_N) break;
        const int nbase = tile * TILE;

        {
            const float4* ag = (const float4*)g_agg;
            float4* xv = (float4*)x_s;
            for (int idx = tid; idx < TILE * HID / 4; idx += NT) {
                int n = nbase + (idx >> 5);
                xv[idx] = (n < NNODES) ? ag[n * (HID/4) + (idx & 31)]
                                       : make_float4(0.f, 0.f, 0.f, 0.f);
            }
        }
        __syncthreads();

        ull acc[4][4];
        #pragma unroll
        for (int i = 0; i < 4; i++) {
            acc[i][0]=b1p[0]; acc[i][1]=b1p[1]; acc[i][2]=b1p[2]; acc[i][3]=b1p[3];
        }
        {
            const float* xb = x_s + ng0 * HID;
            #pragma unroll 2
            for (int k = 0; k < HID; k++) {
                ull a0 = bcast2(xb[k]);
                ull a1 = bcast2(xb[k +   HID]);
                ull a2 = bcast2(xb[k + 2*HID]);
                ull a3 = bcast2(xb[k + 3*HID]);
                const ulonglong2* wp = (const ulonglong2*)(iw1_s + k*HID + c0);
                ulonglong2 w01 = wp[0], w23 = wp[1];
                fma2(acc[0][0],a0,w01.x); fma2(acc[0][1],a0,w01.y); fma2(acc[0][2],a0,w23.x); fma2(acc[0][3],a0,w23.y);
                fma2(acc[1][0],a1,w01.x); fma2(acc[1][1],a1,w01.y); fma2(acc[1][2],a1,w23.x); fma2(acc[1][3],a1,w23.y);
                fma2(acc[2][0],a2,w01.x); fma2(acc[2][1],a2,w01.y); fma2(acc[2][2],a2,w23.x); fma2(acc[2][3],a2,w23.y);
                fma2(acc[3][0],a3,w01.x); fma2(acc[3][1],a3,w01.y); fma2(acc[3][2],a3,w23.x); fma2(acc[3][3],a3,w23.y);
            }
        }
        __syncthreads();
        #pragma unroll
        for (int i = 0; i < 4; i++) {
            float4 o0, o1; float2 v;
            v = unpack2(acc[i][0]); o0.x = silu_f(v.x); o0.y = silu_f(v.y);
            v = unpack2(acc[i][1]); o0.z = silu_f(v.x); o0.w = silu_f(v.y);
            v = unpack2(acc[i][2]); o1.x = silu_f(v.x); o1.y = silu_f(v.y);
            v = unpack2(acc[i][3]); o1.z = silu_f(v.x); o1.w = silu_f(v.y);
            *(float4*)(x_s + (ng0+i)*HID + c0)     = o0;
            *(float4*)(x_s + (ng0+i)*HID + c0 + 4) = o1;
        }
        __syncthreads();

        #pragma unroll
        for (int i = 0; i < 4; i++) {
            acc[i][0]=b2p[0]; acc[i][1]=b2p[1]; acc[i][2]=b2p[2]; acc[i][3]=b2p[3];
        }
        {
            const float* xb = x_s + ng0 * HID;
            #pragma unroll 2
            for (int k = 0; k < HID; k++) {
                ull a0 = bcast2(xb[k]);
                ull a1 = bcast2(xb[k +   HID]);
                ull a2 = bcast2(xb[k + 2*HID]);
                ull a3 = bcast2(xb[k + 3*HID]);
                const ulonglong2* wp = (const ulonglong2*)(iw2_s + k*HID + c0);
                ulonglong2 w01 = wp[0], w23 = wp[1];
                fma2(acc[0][0],a0,w01.x); fma2(acc[0][1],a0,w01.y); fma2(acc[0][2],a0,w23.x); fma2(acc[0][3],a0,w23.y);
                fma2(acc[1][0],a1,w01.x); fma2(acc[1][1],a1,w01.y); fma2(acc[1][2],a1,w23.x); fma2(acc[1][3],a1,w23.y);
                fma2(acc[2][0],a2,w01.x); fma2(acc[2][1],a2,w01.y); fma2(acc[2][2],a2,w23.x); fma2(acc[2][3],a2,w23.y);
                fma2(acc[3][0],a3,w01.x); fma2(acc[3][1],a3,w01.y); fma2(acc[3][2],a3,w23.x); fma2(acc[3][3],a3,w23.y);
            }
        }

        #pragma unroll
        for (int i = 0; i < 4; i++) {
            int n = ng0 + i + nbase;
            if (n >= NNODES) continue;
            float4 h0 = *(const float4*)(hin + n*HID + c0);
            float4 h1 = *(const float4*)(hin + n*HID + c0 + 4);
            float2 v0 = unpack2(acc[i][0]);
            float2 v1 = unpack2(acc[i][1]);
            float2 v2 = unpack2(acc[i][2]);
            float2 v3 = unpack2(acc[i][3]);
            float4 o0 = make_float4(h0.x + v0.x, h0.y + v0.y, h0.z + v1.x, h0.w + v1.y);
            float4 o1 = make_float4(h1.x + v2.x, h1.y + v2.y, h1.z + v3.x, h1.w + v3.y);
            *(float4*)(out + n*HID + c0)     = o0;
            *(float4*)(out + n*HID + c0 + 4) = o1;
        }
    }
}

extern "C" void kernel_launch(void* const* d_in, const int* in_sizes, int n_in,
                              void* d_out, int out_size)
{
    const float* h    = (const float*)d_in[0];
    const float* pos  = (const float*)d_in[1];
    const void*  ei   = d_in[2];
    const float* fw1  = (const float*)d_in[3];
    const float* fb1  = (const float*)d_in[4];
    const float* fw2  = (const float*)d_in[5];
    const float* fb2  = (const float*)d_in[6];
    const float* iw1  = (const float*)d_in[7];
    const float* ib1  = (const float*)d_in[8];
    const float* iw2  = (const float*)d_in[9];
    const float* ib2  = (const float*)d_in[10];
    float* out = (float*)d_out;

    cudaFuncSetAttribute(table_kernel, cudaFuncAttributeMaxDynamicSharedMemorySize, TBL_SMEM_BYTES);
    cudaFuncSetAttribute(node_kernel, cudaFuncAttributeMaxDynamicSharedMemorySize, NODE_SMEM_BYTES);

    zero_kernel<<<1184, 512>>>(ei);
    table_kernel<<<NBINS / TILE, NT, TBL_SMEM_BYTES>>>(fw1, fb1, fw2, fb2);
    gather_kernel<<<GGRID, GNT>>>(h, pos, ei);
    node_kernel<<<GRID_P, NT, NODE_SMEM_BYTES>>>(h, out, iw1, ib1, iw2, ib2);
}

// round 4
// speedup vs baseline: 5.0311x; 1.1488x over previous
#include <cuda_runtime.h>
#include <cuda_fp16.h>
#include <cstdint>

#define NNODES  50000
#define NEDGES  640000
#define HID     128
#define NRBF    50
#define TILE    128
#define NT      512
#define CUTOFF_F 5.0f
#define NTILES_N ((NNODES + TILE - 1) / TILE)
#define GRID_P  152

#define NBINS   16384
#define TSTEP   (CUTOFF_F / (float)(NBINS - 1))
#define TINV    ((float)(NBINS - 1) / CUTOFF_F)

#define RBF_W   (CUTOFF_F / 49.0f)
#define RBF_IW  (49.0f / CUTOFF_F)

#define XTS 132   // padded transpose stride (floats): conflict-free + 16B aligned

typedef unsigned long long ull;

__device__ float  g_agg[NNODES * HID];
__device__ float  g_table[NBINS * HID];   // 8 MB fp32 wf(d)
__device__ __half g_dtab[NBINS * HID];    // 4 MB fp16 slope
__device__ unsigned g_ctr_node;
__device__ int g_is64;

// ---------- packed f32x2 helpers ----------
__device__ __forceinline__ void fma2(ull &acc, ull a, ull b) {
    asm("fma.rn.f32x2 %0, %1, %2, %0;" : "+l"(acc) : "l"(a), "l"(b));
}
__device__ __forceinline__ ull bcast2(float x) {
    ull r; asm("mov.b64 %0, {%1, %1};" : "=l"(r) : "f"(x)); return r;
}
__device__ __forceinline__ ull pack2(float x, float y) {
    ull r; asm("mov.b64 %0, {%1, %2};" : "=l"(r) : "f"(x), "f"(y)); return r;
}
__device__ __forceinline__ float2 unpack2(ull v) {
    float2 f; asm("mov.b64 {%0, %1}, %2;" : "=f"(f.x), "=f"(f.y) : "l"(v)); return f;
}
__device__ __forceinline__ void red4(float* p, float a, float b, float c, float d) {
    asm volatile("red.global.add.v4.f32 [%0], {%1,%2,%3,%4};"
                 :: "l"(p), "f"(a), "f"(b), "f"(c), "f"(d) : "memory");
}
__device__ __forceinline__ float silu_f(float x) {
    return x / (1.0f + __expf(-x));
}

// ---------- zero scratch + counters + dtype flag ----------
__global__ void zero_kernel(const void* ei) {
    if (blockIdx.x == 0 && threadIdx.x == 0) {
        g_ctr_node = 0u;
        const unsigned* u = (const unsigned*)ei;
        unsigned acc = 0;
        #pragma unroll
        for (int i = 0; i < 64; i++) acc |= u[2*i + 1];
        g_is64 = (acc == 0);
    }
    float4* p = (float4*)g_agg;
    const int n = NNODES * HID / 4;
    for (int i = blockIdx.x * blockDim.x + threadIdx.x; i < n; i += gridDim.x * blockDim.x)
        p[i] = make_float4(0.f, 0.f, 0.f, 0.f);
}

// ---------- table build kernel (unchanged microkernel; 128 CTAs, one wave) ----------
#define TBL_SMEM_FLOATS (NRBF*HID + HID*HID + TILE*NRBF + TILE*HID + TILE)
#define TBL_SMEM_BYTES  (TBL_SMEM_FLOATS * 4)

__global__ __launch_bounds__(NT, 1)
void table_kernel(const float* __restrict__ fw1, const float* __restrict__ fb1,
                  const float* __restrict__ fw2, const float* __restrict__ fb2)
{
    extern __shared__ float sm[];
    float* fw1_s  = sm;
    float* fw2_s  = fw1_s + NRBF * HID;
    float* rbf_s  = fw2_s + HID * HID;
    float* s1_s   = rbf_s + TILE * NRBF;
    float* cut_s  = s1_s + TILE * HID;

    const int tid = threadIdx.x;
    const int rbase = blockIdx.x * TILE;

    {
        const float4* w1 = (const float4*)fw1; float4* d1 = (float4*)fw1_s;
        for (int i = tid; i < NRBF*HID/4; i += NT) d1[i] = w1[i];
        const float4* w2 = (const float4*)fw2; float4* d2 = (float4*)fw2_s;
        for (int i = tid; i < HID*HID/4; i += NT) d2[i] = w2[i];
    }
    if (tid < TILE) {
        float d = (float)(rbase + tid) * TSTEP;
        cut_s[tid] = 0.5f * (__cosf(d * (3.14159265358979323846f / CUTOFF_F)) + 1.0f);
    }
    for (int idx = tid; idx < TILE * NRBF; idx += NT) {
        int e = idx / NRBF;
        int k = idx - e * NRBF;
        float d = (float)(rbase + e) * TSTEP;
        float t = (d - (float)k * RBF_W) * RBF_IW;
        rbf_s[idx] = __expf(-0.5f * t * t);
    }
    __syncthreads();

    const int eg0 = (tid >> 4) * 4;
    const int c0  = (tid & 15) * 8;

    ull acc[4][4];
    {
        float4 ba = *(const float4*)(fb1 + c0);
        float4 bb = *(const float4*)(fb1 + c0 + 4);
        ull i0 = pack2(ba.x, ba.y), i1 = pack2(ba.z, ba.w);
        ull i2 = pack2(bb.x, bb.y), i3 = pack2(bb.z, bb.w);
        #pragma unroll
        for (int i = 0; i < 4; i++) { acc[i][0]=i0; acc[i][1]=i1; acc[i][2]=i2; acc[i][3]=i3; }
    }
    {
        const float* rb = rbf_s + eg0 * NRBF;
        #pragma unroll 2
        for (int k = 0; k < NRBF; k++) {
            ull a0 = bcast2(rb[k]);
            ull a1 = bcast2(rb[k +   NRBF]);
            ull a2 = bcast2(rb[k + 2*NRBF]);
            ull a3 = bcast2(rb[k + 3*NRBF]);
            const ulonglong2* wp = (const ulonglong2*)(fw1_s + k*HID + c0);
            ulonglong2 w01 = wp[0], w23 = wp[1];
            fma2(acc[0][0],a0,w01.x); fma2(acc[0][1],a0,w01.y); fma2(acc[0][2],a0,w23.x); fma2(acc[0][3],a0,w23.y);
            fma2(acc[1][0],a1,w01.x); fma2(acc[1][1],a1,w01.y); fma2(acc[1][2],a1,w23.x); fma2(acc[1][3],a1,w23.y);
            fma2(acc[2][0],a2,w01.x); fma2(acc[2][1],a2,w01.y); fma2(acc[2][2],a2,w23.x); fma2(acc[2][3],a2,w23.y);
            fma2(acc[3][0],a3,w01.x); fma2(acc[3][1],a3,w01.y); fma2(acc[3][2],a3,w23.x); fma2(acc[3][3],a3,w23.y);
        }
    }
    #pragma unroll
    for (int i = 0; i < 4; i++) {
        float4 o0, o1; float2 v;
        v = unpack2(acc[i][0]); o0.x = silu_f(v.x); o0.y = silu_f(v.y);
        v = unpack2(acc[i][1]); o0.z = silu_f(v.x); o0.w = silu_f(v.y);
        v = unpack2(acc[i][2]); o1.x = silu_f(v.x); o1.y = silu_f(v.y);
        v = unpack2(acc[i][3]); o1.z = silu_f(v.x); o1.w = silu_f(v.y);
        *(float4*)(s1_s + (eg0+i)*HID + c0)     = o0;
        *(float4*)(s1_s + (eg0+i)*HID + c0 + 4) = o1;
    }
    __syncthreads();

    {
        float4 ba = *(const float4*)(fb2 + c0);
        float4 bb = *(const float4*)(fb2 + c0 + 4);
        ull i0 = pack2(ba.x, ba.y), i1 = pack2(ba.z, ba.w);
        ull i2 = pack2(bb.x, bb.y), i3 = pack2(bb.z, bb.w);
        #pragma unroll
        for (int i = 0; i < 4; i++) { acc[i][0]=i0; acc[i][1]=i1; acc[i][2]=i2; acc[i][3]=i3; }
    }
    {
        const float* sb = s1_s + eg0 * HID;
        #pragma unroll 2
        for (int k = 0; k < HID; k++) {
            ull a0 = bcast2(sb[k]);
            ull a1 = bcast2(sb[k +   HID]);
            ull a2 = bcast2(sb[k + 2*HID]);
            ull a3 = bcast2(sb[k + 3*HID]);
            const ulonglong2* wp = (const ulonglong2*)(fw2_s + k*HID + c0);
            ulonglong2 w01 = wp[0], w23 = wp[1];
            fma2(acc[0][0],a0,w01.x); fma2(acc[0][1],a0,w01.y); fma2(acc[0][2],a0,w23.x); fma2(acc[0][3],a0,w23.y);
            fma2(acc[1][0],a1,w01.x); fma2(acc[1][1],a1,w01.y); fma2(acc[1][2],a1,w23.x); fma2(acc[1][3],a1,w23.y);
            fma2(acc[2][0],a2,w01.x); fma2(acc[2][1],a2,w01.y); fma2(acc[2][2],a2,w23.x); fma2(acc[2][3],a2,w23.y);
            fma2(acc[3][0],a3,w01.x); fma2(acc[3][1],a3,w01.y); fma2(acc[3][2],a3,w23.x); fma2(acc[3][3],a3,w23.y);
        }
    }
    #pragma unroll
    for (int i = 0; i < 4; i++) {
        int r = rbase + eg0 + i;
        float ct = cut_s[eg0 + i];
        float2 v0 = unpack2(acc[i][0]);
        float2 v1 = unpack2(acc[i][1]);
        float2 v2 = unpack2(acc[i][2]);
        float2 v3 = unpack2(acc[i][3]);
        float4 o0 = make_float4(v0.x*ct, v0.y*ct, v1.x*ct, v1.y*ct);
        float4 o1 = make_float4(v2.x*ct, v2.y*ct, v3.x*ct, v3.y*ct);
        *(float4*)(g_table + r*HID + c0)     = o0;
        *(float4*)(g_table + r*HID + c0 + 4) = o1;
    }
}

// ---------- slope table: D[i] = T[i+1]-T[i] in fp16 ----------
__global__ void dtab_kernel() {
    int idx = blockIdx.x * blockDim.x + threadIdx.x;   // over half2 pairs
    const int n2 = NBINS * HID / 2;
    if (idx >= n2) return;
    int base = idx * 2;
    float2 t = *(const float2*)(g_table + base);
    float2 tn = (base + HID < NBINS * HID) ? *(const float2*)(g_table + base + HID)
                                           : t;
    *(__half2*)(g_dtab + base) = __floats2half2_rn(tn.x - t.x, tn.y - t.y);
}

// ---------- edge gather/lerp/scatter ----------
#define GNT 256
#define GGRID 1184

__global__ __launch_bounds__(GNT)
void gather_kernel(const float* __restrict__ hin, const float* __restrict__ pos,
                   const void* __restrict__ ei)
{
    const int is64 = g_is64;
    const int lane16 = threadIdx.x & 15;
    const int c0 = lane16 * 8;
    const int gpb = GNT / 16;
    int g = blockIdx.x * gpb + (threadIdx.x >> 4);
    const int gstride = GGRID * gpb;

    for (; g < NEDGES; g += gstride) {
        int r, c;
        if (is64) {
            r = (int)__ldg((const long long*)ei + g);
            c = (int)__ldg((const long long*)ei + NEDGES + g);
        } else {
            r = __ldg((const int*)ei + g);
            c = __ldg((const int*)ei + NEDGES + g);
        }
        float dx = pos[r*3+0] - pos[c*3+0];
        float dy = pos[r*3+1] - pos[c*3+1];
        float dz = pos[r*3+2] - pos[c*3+2];
        float d  = sqrtf(dx*dx + dy*dy + dz*dz + 1e-8f);
        if (d > CUTOFF_F) continue;

        float t = d * TINV;
        int i0 = (int)t;
        if (i0 > NBINS - 1) i0 = NBINS - 1;
        float fr = t - (float)i0;

        const float* T0 = g_table + i0*HID + c0;
        float4 a0 = *(const float4*)(T0);
        float4 a1 = *(const float4*)(T0 + 4);
        uint4 du = *(const uint4*)(g_dtab + i0*HID + c0);
        float2 d01 = __half22float2(*(__half2*)&du.x);
        float2 d23 = __half22float2(*(__half2*)&du.y);
        float2 d45 = __half22float2(*(__half2*)&du.z);
        float2 d67 = __half22float2(*(__half2*)&du.w);
        float4 h0 = *(const float4*)(hin + c*HID + c0);
        float4 h1 = *(const float4*)(hin + c*HID + c0 + 4);

        float w0 = fmaf(fr, d01.x, a0.x);
        float w1 = fmaf(fr, d01.y, a0.y);
        float w2 = fmaf(fr, d23.x, a0.z);
        float w3 = fmaf(fr, d23.y, a0.w);
        float w4 = fmaf(fr, d45.x, a1.x);
        float w5 = fmaf(fr, d45.y, a1.y);
        float w6 = fmaf(fr, d67.x, a1.z);
        float w7 = fmaf(fr, d67.y, a1.w);

        float* dst = g_agg + r*HID + c0;
        red4(dst,     h0.x*w0, h0.y*w1, h0.z*w2, h0.w*w3);
        red4(dst + 4, h1.x*w4, h1.y*w5, h1.z*w6, h1.w*w7);
    }
}

// ---------- persistent node kernel: warp-owns-columns, transposed x tile ----------
// smem: iw1[128*128] | iw2[128*128] | xT[128*XTS]
#define NODE_SMEM_BYTES ((2 * HID * HID + HID * XTS) * 4)

__global__ __launch_bounds__(NT, 1)
void node_kernel(const float* __restrict__ hin, float* __restrict__ out,
                 const float* __restrict__ iw1, const float* __restrict__ ib1,
                 const float* __restrict__ iw2, const float* __restrict__ ib2)
{
    extern __shared__ float sm[];
    float* iw1_s = sm;
    float* iw2_s = iw1_s + HID * HID;
    float* xT    = iw2_s + HID * HID;     // [HID][XTS], rows = channels, cols = nodes
    __shared__ int s_tile;

    const int tid  = threadIdx.x;
    const int wid  = tid >> 5;      // 0..15 -> owns cols [wid*8, wid*8+8)
    const int lane = tid & 31;      // owns nodes [lane*4, lane*4+4)
    const int c0   = wid * 8;
    const int e0   = lane * 4;

    {
        const float4* w1 = (const float4*)iw1; float4* d1 = (float4*)iw1_s;
        for (int i = tid; i < HID*HID/4; i += NT) d1[i] = w1[i];
        const float4* w2 = (const float4*)iw2; float4* d2 = (float4*)iw2_s;
        for (int i = tid; i < HID*HID/4; i += NT) d2[i] = w2[i];
    }

    // pre-packed biases for this thread's 8 columns
    ull b1p[4], b2p[4];
    {
        float4 ba = *(const float4*)(ib1 + c0);
        float4 bb = *(const float4*)(ib1 + c0 + 4);
        b1p[0] = pack2(ba.x, ba.y); b1p[1] = pack2(ba.z, ba.w);
        b1p[2] = pack2(bb.x, bb.y); b1p[3] = pack2(bb.z, bb.w);
        ba = *(const float4*)(ib2 + c0);
        bb = *(const float4*)(ib2 + c0 + 4);
        b2p[0] = pack2(ba.x, ba.y); b2p[1] = pack2(ba.z, ba.w);
        b2p[2] = pack2(bb.x, bb.y); b2p[3] = pack2(bb.z, bb.w);
    }

    while (true) {
        __syncthreads();
        if (tid == 0) s_tile = (int)atomicAdd(&g_ctr_node, 1u);
        __syncthreads();
        const int tile = s_tile;
        if (tile >= NTILES_N) break;
        const int nbase = tile * TILE;

        // stage agg tile TRANSPOSED: xT[c][n] = agg[nbase+n][c]
        // idx -> n = idx & 127 (lane dim -> conflict-free STS), c4 = idx >> 7
        for (int idx = tid; idx < TILE * (HID/4); idx += NT) {
            int n  = idx & 127;
            int c4 = idx >> 7;
            float4 v = make_float4(0.f,0.f,0.f,0.f);
            int gn = nbase + n;
            if (gn < NNODES) v = __ldg((const float4*)(g_agg + gn*HID + c4*4));
            xT[(c4*4+0)*XTS + n] = v.x;
            xT[(c4*4+1)*XTS + n] = v.y;
            xT[(c4*4+2)*XTS + n] = v.z;
            xT[(c4*4+3)*XTS + n] = v.w;
        }
        __syncthreads();

        // ---- GEMM1: acc[e*4+cp] = cols (c0+2cp, c0+2cp+1) for node e0+e ----
        ull acc[16];
        #pragma unroll
        for (int e = 0; e < 4; e++) {
            acc[e*4+0]=b1p[0]; acc[e*4+1]=b1p[1]; acc[e*4+2]=b1p[2]; acc[e*4+3]=b1p[3];
        }
        #pragma unroll 2
        for (int k = 0; k < HID; k++) {
            float4 av = *(const float4*)(xT + k*XTS + e0);
            ull a0 = bcast2(av.x), a1 = bcast2(av.y), a2 = bcast2(av.z), a3 = bcast2(av.w);
            const ulonglong2* wp = (const ulonglong2*)(iw1_s + k*HID + c0);  // all lanes same addr
            ulonglong2 w01 = wp[0], w23 = wp[1];
            fma2(acc[0],a0,w01.x);  fma2(acc[1],a0,w01.y);  fma2(acc[2],a0,w23.x);  fma2(acc[3],a0,w23.y);
            fma2(acc[4],a1,w01.x);  fma2(acc[5],a1,w01.y);  fma2(acc[6],a1,w23.x);  fma2(acc[7],a1,w23.y);
            fma2(acc[8],a2,w01.x);  fma2(acc[9],a2,w01.y);  fma2(acc[10],a2,w23.x); fma2(acc[11],a2,w23.y);
            fma2(acc[12],a3,w01.x); fma2(acc[13],a3,w01.y); fma2(acc[14],a3,w23.x); fma2(acc[15],a3,w23.y);
        }
        __syncthreads();   // ALL reads of xT complete before in-place overwrite

        // silu + write back transposed: xT[c0+cc][e0..e0+3]
        #pragma unroll
        for (int cp = 0; cp < 4; cp++) {
            float2 v0 = unpack2(acc[0*4+cp]);
            float2 v1 = unpack2(acc[1*4+cp]);
            float2 v2 = unpack2(acc[2*4+cp]);
            float2 v3 = unpack2(acc[3*4+cp]);
            float4 oA = make_float4(silu_f(v0.x), silu_f(v1.x), silu_f(v2.x), silu_f(v3.x));
            float4 oB = make_float4(silu_f(v0.y), silu_f(v1.y), silu_f(v2.y), silu_f(v3.y));
            *(float4*)(xT + (c0 + 2*cp    )*XTS + e0) = oA;
            *(float4*)(xT + (c0 + 2*cp + 1)*XTS + e0) = oB;
        }
        __syncthreads();

        // ---- GEMM2 ----
        #pragma unroll
        for (int e = 0; e < 4; e++) {
            acc[e*4+0]=b2p[0]; acc[e*4+1]=b2p[1]; acc[e*4+2]=b2p[2]; acc[e*4+3]=b2p[3];
        }
        #pragma unroll 2
        for (int k = 0; k < HID; k++) {
            float4 av = *(const float4*)(xT + k*XTS + e0);
            ull a0 = bcast2(av.x), a1 = bcast2(av.y), a2 = bcast2(av.z), a3 = bcast2(av.w);
            const ulonglong2* wp = (const ulonglong2*)(iw2_s + k*HID + c0);
            ulonglong2 w01 = wp[0], w23 = wp[1];
            fma2(acc[0],a0,w01.x);  fma2(acc[1],a0,w01.y);  fma2(acc[2],a0,w23.x);  fma2(acc[3],a0,w23.y);
            fma2(acc[4],a1,w01.x);  fma2(acc[5],a1,w01.y);  fma2(acc[6],a1,w23.x);  fma2(acc[7],a1,w23.y);
            fma2(acc[8],a2,w01.x);  fma2(acc[9],a2,w01.y);  fma2(acc[10],a2,w23.x); fma2(acc[11],a2,w23.y);
            fma2(acc[12],a3,w01.x); fma2(acc[13],a3,w01.y); fma2(acc[14],a3,w23.x); fma2(acc[15],a3,w23.y);
        }

        // ---- epilogue: out = h + result ----
        #pragma unroll
        for (int e = 0; e < 4; e++) {
            int n = nbase + e0 + e;
            if (n >= NNODES) continue;
            float4 h0 = __ldg((const float4*)(hin + n*HID + c0));
            float4 h1 = __ldg((const float4*)(hin + n*HID + c0 + 4));
            float2 v0 = unpack2(acc[e*4+0]);
            float2 v1 = unpack2(acc[e*4+1]);
            float2 v2 = unpack2(acc[e*4+2]);
            float2 v3 = unpack2(acc[e*4+3]);
            float4 o0 = make_float4(h0.x + v0.x, h0.y + v0.y, h0.z + v1.x, h0.w + v1.y);
            float4 o1 = make_float4(h1.x + v2.x, h1.y + v2.y, h1.z + v3.x, h1.w + v3.y);
            *(float4*)(out + n*HID + c0)     = o0;
            *(float4*)(out + n*HID + c0 + 4) = o1;
        }
    }
}

extern "C" void kernel_launch(void* const* d_in, const int* in_sizes, int n_in,
                              void* d_out, int out_size)
{
    const float* h    = (const float*)d_in[0];
    const float* pos  = (const float*)d_in[1];
    const void*  ei   = d_in[2];
    const float* fw1  = (const float*)d_in[3];
    const float* fb1  = (const float*)d_in[4];
    const float* fw2  = (const float*)d_in[5];
    const float* fb2  = (const float*)d_in[6];
    const float* iw1  = (const float*)d_in[7];
    const float* ib1  = (const float*)d_in[8];
    const float* iw2  = (const float*)d_in[9];
    const float* ib2  = (const float*)d_in[10];
    float* out = (float*)d_out;

    cudaFuncSetAttribute(table_kernel, cudaFuncAttributeMaxDynamicSharedMemorySize, TBL_SMEM_BYTES);
    cudaFuncSetAttribute(node_kernel, cudaFuncAttributeMaxDynamicSharedMemorySize, NODE_SMEM_BYTES);

    zero_kernel<<<1184, 512>>>(ei);
    table_kernel<<<NBINS / TILE, NT, TBL_SMEM_BYTES>>>(fw1, fb1, fw2, fb2);
    dtab_kernel<<<(NBINS * HID / 2 + 255) / 256, 256>>>();
    gather_kernel<<<GGRID, GNT>>>(h, pos, ei);
    node_kernel<<<GRID_P, NT, NODE_SMEM_BYTES>>>(h, out, iw1, ib1, iw2, ib2);
}

// round 5
// speedup vs baseline: 5.1623x; 1.0261x over previous
#include <cuda_runtime.h>
#include <cuda_fp16.h>
#include <cstdint>

#define NNODES  50000
#define NEDGES  640000
#define HID     128
#define NRBF    50
#define TILE    128
#define NT      512
#define CUTOFF_F 5.0f
#define NTILES_N ((NNODES + TILE - 1) / TILE)
#define GRID_P  152

#define NBINS   16384
#define TSTEP   (CUTOFF_F / (float)(NBINS - 1))
#define TINV    ((float)(NBINS - 1) / CUTOFF_F)

#define RBF_W   (CUTOFF_F / 49.0f)
#define RBF_IW  (49.0f / CUTOFF_F)

#define XTS 132   // padded transpose stride (floats)

typedef unsigned long long ull;

__device__ float   g_agg[NNODES * HID];
__device__ float   g_table[NBINS * HID];    // fp32 wf(d) (build stage)
__device__ __half2 g_htab[NBINS * HID];     // 8 MB: {value, slope} fp16 per channel
__device__ unsigned g_ctr_node;
__device__ int g_is64;

// ---------- packed f32x2 helpers ----------
__device__ __forceinline__ void fma2(ull &acc, ull a, ull b) {
    asm("fma.rn.f32x2 %0, %1, %2, %0;" : "+l"(acc) : "l"(a), "l"(b));
}
__device__ __forceinline__ ull bcast2(float x) {
    ull r; asm("mov.b64 %0, {%1, %1};" : "=l"(r) : "f"(x)); return r;
}
__device__ __forceinline__ ull pack2(float x, float y) {
    ull r; asm("mov.b64 %0, {%1, %2};" : "=l"(r) : "f"(x), "f"(y)); return r;
}
__device__ __forceinline__ float2 unpack2(ull v) {
    float2 f; asm("mov.b64 {%0, %1}, %2;" : "=f"(f.x), "=f"(f.y) : "l"(v)); return f;
}
__device__ __forceinline__ void red4(float* p, float a, float b, float c, float d) {
    asm volatile("red.global.add.v4.f32 [%0], {%1,%2,%3,%4};"
                 :: "l"(p), "f"(a), "f"(b), "f"(c), "f"(d) : "memory");
}
__device__ __forceinline__ float silu_f(float x) {
    return x / (1.0f + __expf(-x));
}

// ---------- zero scratch + counters + dtype flag ----------
__global__ void zero_kernel(const void* ei) {
    if (blockIdx.x == 0 && threadIdx.x == 0) {
        g_ctr_node = 0u;
        const unsigned* u = (const unsigned*)ei;
        unsigned acc = 0;
        #pragma unroll
        for (int i = 0; i < 64; i++) acc |= u[2*i + 1];
        g_is64 = (acc == 0);
    }
    float4* p = (float4*)g_agg;
    const int n = NNODES * HID / 4;
    for (int i = blockIdx.x * blockDim.x + threadIdx.x; i < n; i += gridDim.x * blockDim.x)
        p[i] = make_float4(0.f, 0.f, 0.f, 0.f);
}

// ---------- table build kernel ----------
#define TBL_SMEM_FLOATS (NRBF*HID + HID*HID + TILE*NRBF + TILE*HID + TILE)
#define TBL_SMEM_BYTES  (TBL_SMEM_FLOATS * 4)

__global__ __launch_bounds__(NT, 1)
void table_kernel(const float* __restrict__ fw1, const float* __restrict__ fb1,
                  const float* __restrict__ fw2, const float* __restrict__ fb2)
{
    extern __shared__ float sm[];
    float* fw1_s  = sm;
    float* fw2_s  = fw1_s + NRBF * HID;
    float* rbf_s  = fw2_s + HID * HID;
    float* s1_s   = rbf_s + TILE * NRBF;
    float* cut_s  = s1_s + TILE * HID;

    const int tid = threadIdx.x;
    const int rbase = blockIdx.x * TILE;

    {
        const float4* w1 = (const float4*)fw1; float4* d1 = (float4*)fw1_s;
        for (int i = tid; i < NRBF*HID/4; i += NT) d1[i] = w1[i];
        const float4* w2 = (const float4*)fw2; float4* d2 = (float4*)fw2_s;
        for (int i = tid; i < HID*HID/4; i += NT) d2[i] = w2[i];
    }
    if (tid < TILE) {
        float d = (float)(rbase + tid) * TSTEP;
        cut_s[tid] = 0.5f * (__cosf(d * (3.14159265358979323846f / CUTOFF_F)) + 1.0f);
    }
    for (int idx = tid; idx < TILE * NRBF; idx += NT) {
        int e = idx / NRBF;
        int k = idx - e * NRBF;
        float d = (float)(rbase + e) * TSTEP;
        float t = (d - (float)k * RBF_W) * RBF_IW;
        rbf_s[idx] = __expf(-0.5f * t * t);
    }
    __syncthreads();

    const int eg0 = (tid >> 4) * 4;
    const int c0  = (tid & 15) * 8;

    ull acc[4][4];
    {
        float4 ba = *(const float4*)(fb1 + c0);
        float4 bb = *(const float4*)(fb1 + c0 + 4);
        ull i0 = pack2(ba.x, ba.y), i1 = pack2(ba.z, ba.w);
        ull i2 = pack2(bb.x, bb.y), i3 = pack2(bb.z, bb.w);
        #pragma unroll
        for (int i = 0; i < 4; i++) { acc[i][0]=i0; acc[i][1]=i1; acc[i][2]=i2; acc[i][3]=i3; }
    }
    {
        const float* rb = rbf_s + eg0 * NRBF;
        #pragma unroll 2
        for (int k = 0; k < NRBF; k++) {
            ull a0 = bcast2(rb[k]);
            ull a1 = bcast2(rb[k +   NRBF]);
            ull a2 = bcast2(rb[k + 2*NRBF]);
            ull a3 = bcast2(rb[k + 3*NRBF]);
            const ulonglong2* wp = (const ulonglong2*)(fw1_s + k*HID + c0);
            ulonglong2 w01 = wp[0], w23 = wp[1];
            fma2(acc[0][0],a0,w01.x); fma2(acc[0][1],a0,w01.y); fma2(acc[0][2],a0,w23.x); fma2(acc[0][3],a0,w23.y);
            fma2(acc[1][0],a1,w01.x); fma2(acc[1][1],a1,w01.y); fma2(acc[1][2],a1,w23.x); fma2(acc[1][3],a1,w23.y);
            fma2(acc[2][0],a2,w01.x); fma2(acc[2][1],a2,w01.y); fma2(acc[2][2],a2,w23.x); fma2(acc[2][3],a2,w23.y);
            fma2(acc[3][0],a3,w01.x); fma2(acc[3][1],a3,w01.y); fma2(acc[3][2],a3,w23.x); fma2(acc[3][3],a3,w23.y);
        }
    }
    #pragma unroll
    for (int i = 0; i < 4; i++) {
        float4 o0, o1; float2 v;
        v = unpack2(acc[i][0]); o0.x = silu_f(v.x); o0.y = silu_f(v.y);
        v = unpack2(acc[i][1]); o0.z = silu_f(v.x); o0.w = silu_f(v.y);
        v = unpack2(acc[i][2]); o1.x = silu_f(v.x); o1.y = silu_f(v.y);
        v = unpack2(acc[i][3]); o1.z = silu_f(v.x); o1.w = silu_f(v.y);
        *(float4*)(s1_s + (eg0+i)*HID + c0)     = o0;
        *(float4*)(s1_s + (eg0+i)*HID + c0 + 4) = o1;
    }
    __syncthreads();

    {
        float4 ba = *(const float4*)(fb2 + c0);
        float4 bb = *(const float4*)(fb2 + c0 + 4);
        ull i0 = pack2(ba.x, ba.y), i1 = pack2(ba.z, ba.w);
        ull i2 = pack2(bb.x, bb.y), i3 = pack2(bb.z, bb.w);
        #pragma unroll
        for (int i = 0; i < 4; i++) { acc[i][0]=i0; acc[i][1]=i1; acc[i][2]=i2; acc[i][3]=i3; }
    }
    {
        const float* sb = s1_s + eg0 * HID;
        #pragma unroll 2
        for (int k = 0; k < HID; k++) {
            ull a0 = bcast2(sb[k]);
            ull a1 = bcast2(sb[k +   HID]);
            ull a2 = bcast2(sb[k + 2*HID]);
            ull a3 = bcast2(sb[k + 3*HID]);
            const ulonglong2* wp = (const ulonglong2*)(fw2_s + k*HID + c0);
            ulonglong2 w01 = wp[0], w23 = wp[1];
            fma2(acc[0][0],a0,w01.x); fma2(acc[0][1],a0,w01.y); fma2(acc[0][2],a0,w23.x); fma2(acc[0][3],a0,w23.y);
            fma2(acc[1][0],a1,w01.x); fma2(acc[1][1],a1,w01.y); fma2(acc[1][2],a1,w23.x); fma2(acc[1][3],a1,w23.y);
            fma2(acc[2][0],a2,w01.x); fma2(acc[2][1],a2,w01.y); fma2(acc[2][2],a2,w23.x); fma2(acc[2][3],a2,w23.y);
            fma2(acc[3][0],a3,w01.x); fma2(acc[3][1],a3,w01.y); fma2(acc[3][2],a3,w23.x); fma2(acc[3][3],a3,w23.y);
        }
    }
    #pragma unroll
    for (int i = 0; i < 4; i++) {
        int r = rbase + eg0 + i;
        float ct = cut_s[eg0 + i];
        float2 v0 = unpack2(acc[i][0]);
        float2 v1 = unpack2(acc[i][1]);
        float2 v2 = unpack2(acc[i][2]);
        float2 v3 = unpack2(acc[i][3]);
        float4 o0 = make_float4(v0.x*ct, v0.y*ct, v1.x*ct, v1.y*ct);
        float4 o1 = make_float4(v2.x*ct, v2.y*ct, v3.x*ct, v3.y*ct);
        *(float4*)(g_table + r*HID + c0)     = o0;
        *(float4*)(g_table + r*HID + c0 + 4) = o1;
    }
}

// ---------- interleaved fp16 {value, slope} table ----------
__global__ void htab_kernel() {
    int idx = blockIdx.x * blockDim.x + threadIdx.x;   // channel-element index
    const int n = NBINS * HID;
    if (idx >= n) return;
    float v = g_table[idx];
    float s = (idx + HID < n) ? (g_table[idx + HID] - v) : 0.f;
    g_htab[idx] = __floats2half2_rn(v, s);
}

// ---------- edge gather/lerp/scatter ----------
#define GNT 256
#define GGRID 1184

__global__ __launch_bounds__(GNT)
void gather_kernel(const float* __restrict__ hin, const float* __restrict__ pos,
                   const void* __restrict__ ei)
{
    const int is64 = g_is64;
    const int lane16 = threadIdx.x & 15;
    const int c0 = lane16 * 8;
    const int gpb = GNT / 16;
    int g = blockIdx.x * gpb + (threadIdx.x >> 4);
    const int gstride = GGRID * gpb;

    for (; g < NEDGES; g += gstride) {
        int r, c;
        if (is64) {
            r = (int)__ldg((const long long*)ei + g);
            c = (int)__ldg((const long long*)ei + NEDGES + g);
        } else {
            r = __ldg((const int*)ei + g);
            c = __ldg((const int*)ei + NEDGES + g);
        }
        float dx = pos[r*3+0] - pos[c*3+0];
        float dy = pos[r*3+1] - pos[c*3+1];
        float dz = pos[r*3+2] - pos[c*3+2];
        float d  = sqrtf(dx*dx + dy*dy + dz*dz + 1e-8f);
        if (d > CUTOFF_F) continue;

        float t = d * TINV;
        int i0 = (int)t;
        if (i0 > NBINS - 1) i0 = NBINS - 1;
        float fr = t - (float)i0;

        const uint4* Tp = (const uint4*)(g_htab + i0*HID + c0);
        uint4 q0 = Tp[0];          // channels c0..c0+3: {val,slope} half2 each
        uint4 q1 = Tp[1];          // channels c0+4..c0+7
        float4 h0 = *(const float4*)(hin + c*HID + c0);
        float4 h1 = *(const float4*)(hin + c*HID + c0 + 4);

        float2 t0 = __half22float2(*(__half2*)&q0.x);
        float2 t1 = __half22float2(*(__half2*)&q0.y);
        float2 t2 = __half22float2(*(__half2*)&q0.z);
        float2 t3 = __half22float2(*(__half2*)&q0.w);
        float2 t4 = __half22float2(*(__half2*)&q1.x);
        float2 t5 = __half22float2(*(__half2*)&q1.y);
        float2 t6 = __half22float2(*(__half2*)&q1.z);
        float2 t7 = __half22float2(*(__half2*)&q1.w);

        float w0 = fmaf(fr, t0.y, t0.x);
        float w1 = fmaf(fr, t1.y, t1.x);
        float w2 = fmaf(fr, t2.y, t2.x);
        float w3 = fmaf(fr, t3.y, t3.x);
        float w4 = fmaf(fr, t4.y, t4.x);
        float w5 = fmaf(fr, t5.y, t5.x);
        float w6 = fmaf(fr, t6.y, t6.x);
        float w7 = fmaf(fr, t7.y, t7.x);

        float* dst = g_agg + r*HID + c0;
        red4(dst,     h0.x*w0, h0.y*w1, h0.z*w2, h0.w*w3);
        red4(dst + 4, h1.x*w4, h1.y*w5, h1.z*w6, h1.w*w7);
    }
}

// ---------- persistent node kernel: warp-owns-columns, transposed x tile ----------
#define NODE_SMEM_BYTES ((2 * HID * HID + HID * XTS) * 4)

__global__ __launch_bounds__(NT, 1)
void node_kernel(const float* __restrict__ hin, float* __restrict__ out,
                 const float* __restrict__ iw1, const float* __restrict__ ib1,
                 const float* __restrict__ iw2, const float* __restrict__ ib2)
{
    extern __shared__ float sm[];
    float* iw1_s = sm;
    float* iw2_s = iw1_s + HID * HID;
    float* xT    = iw2_s + HID * HID;
    __shared__ int s_tile;

    const int tid  = threadIdx.x;
    const int wid  = tid >> 5;
    const int lane = tid & 31;
    const int c0   = wid * 8;
    const int e0   = lane * 4;

    {
        const float4* w1 = (const float4*)iw1; float4* d1 = (float4*)iw1_s;
        for (int i = tid; i < HID*HID/4; i += NT) d1[i] = w1[i];
        const float4* w2 = (const float4*)iw2; float4* d2 = (float4*)iw2_s;
        for (int i = tid; i < HID*HID/4; i += NT) d2[i] = w2[i];
    }

    ull b1p[4], b2p[4];
    {
        float4 ba = *(const float4*)(ib1 + c0);
        float4 bb = *(const float4*)(ib1 + c0 + 4);
        b1p[0] = pack2(ba.x, ba.y); b1p[1] = pack2(ba.z, ba.w);
        b1p[2] = pack2(bb.x, bb.y); b1p[3] = pack2(bb.z, bb.w);
        ba = *(const float4*)(ib2 + c0);
        bb = *(const float4*)(ib2 + c0 + 4);
        b2p[0] = pack2(ba.x, ba.y); b2p[1] = pack2(ba.z, ba.w);
        b2p[2] = pack2(bb.x, bb.y); b2p[3] = pack2(bb.z, bb.w);
    }

    while (true) {
        __syncthreads();
        if (tid == 0) s_tile = (int)atomicAdd(&g_ctr_node, 1u);
        __syncthreads();
        const int tile = s_tile;
        if (tile >= NTILES_N) break;
        const int nbase = tile * TILE;

        for (int idx = tid; idx < TILE * (HID/4); idx += NT) {
            int n  = idx & 127;
            int c4 = idx >> 7;
            float4 v = make_float4(0.f,0.f,0.f,0.f);
            int gn = nbase + n;
            if (gn < NNODES) v = __ldg((const float4*)(g_agg + gn*HID + c4*4));
            xT[(c4*4+0)*XTS + n] = v.x;
            xT[(c4*4+1)*XTS + n] = v.y;
            xT[(c4*4+2)*XTS + n] = v.z;
            xT[(c4*4+3)*XTS + n] = v.w;
        }
        __syncthreads();

        // ---- GEMM1, k unrolled by 4 ----
        ull acc[16];
        #pragma unroll
        for (int e = 0; e < 4; e++) {
            acc[e*4+0]=b1p[0]; acc[e*4+1]=b1p[1]; acc[e*4+2]=b1p[2]; acc[e*4+3]=b1p[3];
        }
        for (int k = 0; k < HID; k += 4) {
            float4 av[4];
            ulonglong2 w01[4], w23[4];
            #pragma unroll
            for (int u = 0; u < 4; u++) {
                av[u] = *(const float4*)(xT + (k+u)*XTS + e0);
                const ulonglong2* wp = (const ulonglong2*)(iw1_s + (k+u)*HID + c0);
                w01[u] = wp[0]; w23[u] = wp[1];
            }
            #pragma unroll
            for (int u = 0; u < 4; u++) {
                ull a0 = bcast2(av[u].x), a1 = bcast2(av[u].y), a2 = bcast2(av[u].z), a3 = bcast2(av[u].w);
                fma2(acc[0],a0,w01[u].x);  fma2(acc[1],a0,w01[u].y);  fma2(acc[2],a0,w23[u].x);  fma2(acc[3],a0,w23[u].y);
                fma2(acc[4],a1,w01[u].x);  fma2(acc[5],a1,w01[u].y);  fma2(acc[6],a1,w23[u].x);  fma2(acc[7],a1,w23[u].y);
                fma2(acc[8],a2,w01[u].x);  fma2(acc[9],a2,w01[u].y);  fma2(acc[10],a2,w23[u].x); fma2(acc[11],a2,w23[u].y);
                fma2(acc[12],a3,w01[u].x); fma2(acc[13],a3,w01[u].y); fma2(acc[14],a3,w23[u].x); fma2(acc[15],a3,w23[u].y);
            }
        }
        __syncthreads();

        #pragma unroll
        for (int cp = 0; cp < 4; cp++) {
            float2 v0 = unpack2(acc[0*4+cp]);
            float2 v1 = unpack2(acc[1*4+cp]);
            float2 v2 = unpack2(acc[2*4+cp]);
            float2 v3 = unpack2(acc[3*4+cp]);
            float4 oA = make_float4(silu_f(v0.x), silu_f(v1.x), silu_f(v2.x), silu_f(v3.x));
            float4 oB = make_float4(silu_f(v0.y), silu_f(v1.y), silu_f(v2.y), silu_f(v3.y));
            *(float4*)(xT + (c0 + 2*cp    )*XTS + e0) = oA;
            *(float4*)(xT + (c0 + 2*cp + 1)*XTS + e0) = oB;
        }
        __syncthreads();

        // ---- GEMM2, k unrolled by 4 ----
        #pragma unroll
        for (int e = 0; e < 4; e++) {
            acc[e*4+0]=b2p[0]; acc[e*4+1]=b2p[1]; acc[e*4+2]=b2p[2]; acc[e*4+3]=b2p[3];
        }
        for (int k = 0; k < HID; k += 4) {
            float4 av[4];
            ulonglong2 w01[4], w23[4];
            #pragma unroll
            for (int u = 0; u < 4; u++) {
                av[u] = *(const float4*)(xT + (k+u)*XTS + e0);
                const ulonglong2* wp = (const ulonglong2*)(iw2_s + (k+u)*HID + c0);
                w01[u] = wp[0]; w23[u] = wp[1];
            }
            #pragma unroll
            for (int u = 0; u < 4; u++) {
                ull a0 = bcast2(av[u].x), a1 = bcast2(av[u].y), a2 = bcast2(av[u].z), a3 = bcast2(av[u].w);
                fma2(acc[0],a0,w01[u].x);  fma2(acc[1],a0,w01[u].y);  fma2(acc[2],a0,w23[u].x);  fma2(acc[3],a0,w23[u].y);
                fma2(acc[4],a1,w01[u].x);  fma2(acc[5],a1,w01[u].y);  fma2(acc[6],a1,w23[u].x);  fma2(acc[7],a1,w23[u].y);
                fma2(acc[8],a2,w01[u].x);  fma2(acc[9],a2,w01[u].y);  fma2(acc[10],a2,w23[u].x); fma2(acc[11],a2,w23[u].y);
                fma2(acc[12],a3,w01[u].x); fma2(acc[13],a3,w01[u].y); fma2(acc[14],a3,w23[u].x); fma2(acc[15],a3,w23[u].y);
            }
        }

        #pragma unroll
        for (int e = 0; e < 4; e++) {
            int n = nbase + e0 + e;
            if (n >= NNODES) continue;
            float4 h0 = __ldg((const float4*)(hin + n*HID + c0));
            float4 h1 = __ldg((const float4*)(hin + n*HID + c0 + 4));
            float2 v0 = unpack2(acc[e*4+0]);
            float2 v1 = unpack2(acc[e*4+1]);
            float2 v2 = unpack2(acc[e*4+2]);
            float2 v3 = unpack2(acc[e*4+3]);
            float4 o0 = make_float4(h0.x + v0.x, h0.y + v0.y, h0.z + v1.x, h0.w + v1.y);
            float4 o1 = make_float4(h1.x + v2.x, h1.y + v2.y, h1.z + v3.x, h1.w + v3.y);
            *(float4*)(out + n*HID + c0)     = o0;
            *(float4*)(out + n*HID + c0 + 4) = o1;
        }
    }
}

extern "C" void kernel_launch(void* const* d_in, const int* in_sizes, int n_in,
                              void* d_out, int out_size)
{
    const float* h    = (const float*)d_in[0];
    const float* pos  = (const float*)d_in[1];
    const void*  ei   = d_in[2];
    const float* fw1  = (const float*)d_in[3];
    const float* fb1  = (const float*)d_in[4];
    const float* fw2  = (const float*)d_in[5];
    const float* fb2  = (const float*)d_in[6];
    const float* iw1  = (const float*)d_in[7];
    const float* ib1  = (const float*)d_in[8];
    const float* iw2  = (const float*)d_in[9];
    const float* ib2  = (const float*)d_in[10];
    float* out = (float*)d_out;

    cudaFuncSetAttribute(table_kernel, cudaFuncAttributeMaxDynamicSharedMemorySize, TBL_SMEM_BYTES);
    cudaFuncSetAttribute(node_kernel, cudaFuncAttributeMaxDynamicSharedMemorySize, NODE_SMEM_BYTES);

    zero_kernel<<<1184, 512>>>(ei);
    table_kernel<<<NBINS / TILE, NT, TBL_SMEM_BYTES>>>(fw1, fb1, fw2, fb2);
    htab_kernel<<<(NBINS * HID + 255) / 256, 256>>>();
    gather_kernel<<<GGRID, GNT>>>(h, pos, ei);
    node_kernel<<<GRID_P, NT, NODE_SMEM_BYTES>>>(h, out, iw1, ib1, iw2, ib2);
}